// round 6
// baseline (speedup 1.0000x reference)
#include <cuda_runtime.h>
#include <cuda_bf16.h>
#include <cuda_fp16.h>
#include <cstdint>

#define B_   4
#define S_   2048
#define DIN  1024
#define DM   1024
#define H_   16
#define HD_  64
#define MX   (B_ * S_)   // 8192

// ---------------- scratch (static device arrays: no allocs) ----------------
__device__ __nv_bfloat16 g_xhi[3][(size_t)MX * DIN];
__device__ __nv_bfloat16 g_xlo[3][(size_t)MX * DIN];
__device__ __nv_bfloat16 g_whi[3][(size_t)DM * DIN];
__device__ __nv_bfloat16 g_wlo[3][(size_t)DM * DIN];
// projected tensors (fp16). q: hi/lo split, k: hi only, v: transposed hi/lo
__device__ __half g_qhi[(size_t)64 * S_ * HD_];
__device__ __half g_qlo[(size_t)64 * S_ * HD_];
__device__ __half g_kh [(size_t)64 * S_ * HD_];
__device__ __half g_vthi[(size_t)64 * HD_ * S_];
__device__ __half g_vtlo[(size_t)64 * HD_ * S_];

// ---------------- PTX helpers (baseline sm_80-class ISA only) --------------
__device__ __forceinline__ uint32_t smem_u32(const void* p) {
    uint32_t a;
    asm("{ .reg .u64 t; cvta.to.shared.u64 t, %1; cvt.u32.u64 %0, t; }"
        : "=r"(a) : "l"(p));
    return a;
}

#define CP16(dst, src) \
    asm volatile("cp.async.cg.shared.global [%0], [%1], 16;" \
                 :: "r"(dst), "l"(src) : "memory")
#define CP_COMMIT() asm volatile("cp.async.commit_group;" ::: "memory")
#define CP_WAIT1()  asm volatile("cp.async.wait_group 1;" ::: "memory")
#define CP_WAIT0()  asm volatile("cp.async.wait_group 0;" ::: "memory")

#define LDSM_X4(r0, r1, r2, r3, a) \
    asm volatile("ldmatrix.sync.aligned.m8n8.x4.shared.b16 {%0,%1,%2,%3}, [%4];" \
                 : "=r"(r0), "=r"(r1), "=r"(r2), "=r"(r3) : "r"(a))
#define LDSM_X2(r0, r1, a) \
    asm volatile("ldmatrix.sync.aligned.m8n8.x2.shared.b16 {%0,%1}, [%2];" \
                 : "=r"(r0), "=r"(r1) : "r"(a))

#define MMA_BF16(c, a, b) \
    asm volatile("mma.sync.aligned.m16n8k16.row.col.f32.bf16.bf16.f32 " \
                 "{%0,%1,%2,%3}, {%4,%5,%6,%7}, {%8,%9}, {%0,%1,%2,%3};" \
                 : "+f"((c)[0]), "+f"((c)[1]), "+f"((c)[2]), "+f"((c)[3]) \
                 : "r"((a)[0]), "r"((a)[1]), "r"((a)[2]), "r"((a)[3]), \
                   "r"((b)[0]), "r"((b)[1]))
#define MMA_F16S(c, a, b0v, b1v) \
    asm volatile("mma.sync.aligned.m16n8k16.row.col.f32.f16.f16.f32 " \
                 "{%0,%1,%2,%3}, {%4,%5,%6,%7}, {%8,%9}, {%0,%1,%2,%3};" \
                 : "+f"((c)[0]), "+f"((c)[1]), "+f"((c)[2]), "+f"((c)[3]) \
                 : "r"((a)[0]), "r"((a)[1]), "r"((a)[2]), "r"((a)[3]), \
                   "r"(b0v), "r"(b1v))

#define SWZ(x) ((uint32_t)(x) ^ ((((uint32_t)(x)) >> 3) & 0x70))

// fast e^x on the FMA pipe (x <= 0 path; clamped)
__device__ __forceinline__ float fexp(float x) {
    float y = x * 1.44269504f;
    y = fmaxf(y, -100.f);
    float t = y + 12582912.0f;
    float nf = t - 12582912.0f;
    float f = y - nf;
    uint32_t sc = (__float_as_uint(t) << 23) + 0x3F800000u;
    float p = fmaf(f, 0.0096181291f, 0.0555041087f);
    p = fmaf(f, p, 0.2402265069f);
    p = fmaf(f, p, 0.6931471806f);
    p = fmaf(f, p, 1.0f);
    return p * __uint_as_float(sc);
}

__device__ __forceinline__ uint32_t packhf(float x, float y) {
    __half2 h = __floats2half2_rn(x, y);
    return *(uint32_t*)&h;
}

// ---------------------------------------------------------------------------
// fp32 -> bf16 hi/lo split for X inputs. blockIdx.y selects slot.
// ---------------------------------------------------------------------------
__global__ __launch_bounds__(256)
void conv_x_kernel(const float* __restrict__ Q, const float* __restrict__ K,
                   const float* __restrict__ V)
{
    const int slot = blockIdx.y;
    const float* X = (slot == 0) ? Q : (slot == 1) ? K : V;
    size_t i = (size_t)blockIdx.x * 256 + threadIdx.x;
    float4 v = ((const float4*)X)[i];
    __nv_bfloat16 h0 = __float2bfloat16(v.x), h1 = __float2bfloat16(v.y);
    __nv_bfloat16 h2 = __float2bfloat16(v.z), h3 = __float2bfloat16(v.w);
    __nv_bfloat16 l0 = __float2bfloat16(v.x - __bfloat162float(h0));
    __nv_bfloat16 l1 = __float2bfloat16(v.y - __bfloat162float(h1));
    __nv_bfloat16 l2 = __float2bfloat16(v.z - __bfloat162float(h2));
    __nv_bfloat16 l3 = __float2bfloat16(v.w - __bfloat162float(h3));
    __nv_bfloat162* hp = reinterpret_cast<__nv_bfloat162*>(g_xhi[slot] + i * 4);
    __nv_bfloat162* lp = reinterpret_cast<__nv_bfloat162*>(g_xlo[slot] + i * 4);
    __nv_bfloat162 a; a.x = h0; a.y = h1; hp[0] = a;
    __nv_bfloat162 b; b.x = h2; b.y = h3; hp[1] = b;
    __nv_bfloat162 c; c.x = l0; c.y = l1; lp[0] = c;
    __nv_bfloat162 d; d.x = l2; d.y = l3; lp[1] = d;
}

// ---------------------------------------------------------------------------
// W [K][N] fp32 -> transposed [N][K] bf16 hi/lo. blockIdx.z selects slot.
// ---------------------------------------------------------------------------
__global__ __launch_bounds__(256)
void conv_w_kernel(const float* __restrict__ WQ, const float* __restrict__ WK,
                   const float* __restrict__ WV)
{
    __shared__ float t[32][33];
    const int slot = blockIdx.z;
    const float* W = (slot == 0) ? WQ : (slot == 1) ? WK : WV;
    const int n0 = blockIdx.x * 32, k0 = blockIdx.y * 32;
    const int tx = threadIdx.x & 31, ty = threadIdx.x >> 5;
#pragma unroll
    for (int r = 0; r < 32; r += 8)
        t[ty + r][tx] = W[(size_t)(k0 + ty + r) * DM + n0 + tx];
    __syncthreads();
#pragma unroll
    for (int r = 0; r < 32; r += 8) {
        int n = ty + r;
        float x = t[tx][n];
        __nv_bfloat16 h = __float2bfloat16(x);
        float l = x - __bfloat162float(h);
        size_t o = (size_t)(n0 + n) * DIN + k0 + tx;
        g_whi[slot][o] = h;
        g_wlo[slot][o] = __float2bfloat16(l);
    }
}

// ---------------------------------------------------------------------------
// HMMA projection GEMM (bf16 3-term). blockIdx.z = which. fp16 epilogue:
// which==0: q*0.125 -> g_qhi/qlo [bh][s][hd]
// which==1: k       -> g_kh (hi only)
// which==2: v       -> g_vthi/vtlo transposed [bh][hd][s]
// ---------------------------------------------------------------------------
#define PROJ_TILE_B   10240
#define PROJ_BUF_B    (4 * PROJ_TILE_B)
#define PROJ_SMEM     (2 * PROJ_BUF_B)

__global__ __launch_bounds__(256)
void proj_mma_kernel(const float* __restrict__ bq, const float* __restrict__ bk,
                     const float* __restrict__ bv)
{
    extern __shared__ char dsm[];
    const uint32_t sbase = smem_u32(dsm);

    const int which = blockIdx.z;
    const float* bias = (which == 0) ? bq : (which == 1) ? bk : bv;
    const __nv_bfloat16* Ah = g_xhi[which];
    const __nv_bfloat16* Al = g_xlo[which];
    const __nv_bfloat16* Bh = g_whi[which];
    const __nv_bfloat16* Bl = g_wlo[which];

    const int tid  = threadIdx.x;
    const int wid  = tid >> 5, lane = tid & 31;
    const int wm   = wid & 1;
    const int wn   = wid >> 1;
    const int row0 = blockIdx.y * 128, col0 = blockIdx.x * 128;

    const int lrow  = tid >> 1;
    const int lhalf = tid & 1;
    const uint32_t sdst = (uint32_t)(lrow * 80 + lhalf * 32);
    const char* gA_h = (const char*)(Ah + (size_t)(row0 + lrow) * DIN) + lhalf * 32;
    const char* gA_l = (const char*)(Al + (size_t)(row0 + lrow) * DIN) + lhalf * 32;
    const char* gB_h = (const char*)(Bh + (size_t)(col0 + lrow) * DIN) + lhalf * 32;
    const char* gB_l = (const char*)(Bl + (size_t)(col0 + lrow) * DIN) + lhalf * 32;

    const int r8 = lane & 7;
    const int ami = lane >> 3;
    const uint32_t a_off = (uint32_t)(((wm * 64 + (ami & 1) * 8 + r8) * 40
                                       + (ami >> 1) * 8) * 2);
    const int bmi = (lane >> 3) & 1;
    const uint32_t b_off = (uint32_t)(((wn * 32 + r8) * 40 + bmi * 8) * 2);

    float acc[4][4][4];
#pragma unroll
    for (int i = 0; i < 4; ++i)
#pragma unroll
        for (int j = 0; j < 4; ++j)
            acc[i][j][0] = acc[i][j][1] = acc[i][j][2] = acc[i][j][3] = 0.f;

    {
        uint32_t b0 = sbase;
        CP16(b0 + sdst,                    gA_h);
        CP16(b0 + sdst + 16,               gA_h + 16);
        CP16(b0 + PROJ_TILE_B + sdst,      gA_l);
        CP16(b0 + PROJ_TILE_B + sdst + 16, gA_l + 16);
        CP16(b0 + 2 * PROJ_TILE_B + sdst,      gB_h);
        CP16(b0 + 2 * PROJ_TILE_B + sdst + 16, gB_h + 16);
        CP16(b0 + 3 * PROJ_TILE_B + sdst,      gB_l);
        CP16(b0 + 3 * PROJ_TILE_B + sdst + 16, gB_l + 16);
        CP_COMMIT();
    }

    for (int c = 0; c < 32; ++c) {
        const uint32_t bufb = sbase + (uint32_t)(c & 1) * PROJ_BUF_B;
        if (c + 1 < 32) {
            const uint32_t nb = sbase + (uint32_t)((c + 1) & 1) * PROJ_BUF_B;
            const int kb = (c + 1) * 64;
            CP16(nb + sdst,                    gA_h + kb);
            CP16(nb + sdst + 16,               gA_h + kb + 16);
            CP16(nb + PROJ_TILE_B + sdst,      gA_l + kb);
            CP16(nb + PROJ_TILE_B + sdst + 16, gA_l + kb + 16);
            CP16(nb + 2 * PROJ_TILE_B + sdst,      gB_h + kb);
            CP16(nb + 2 * PROJ_TILE_B + sdst + 16, gB_h + kb + 16);
            CP16(nb + 3 * PROJ_TILE_B + sdst,      gB_l + kb);
            CP16(nb + 3 * PROJ_TILE_B + sdst + 16, gB_l + kb + 16);
            CP_COMMIT();
            CP_WAIT1();
        } else {
            CP_WAIT0();
        }
        __syncthreads();

#pragma unroll
        for (int ks = 0; ks < 32; ks += 16) {
            const uint32_t ab = bufb + a_off + (uint32_t)(ks * 2);
            const uint32_t bb = bufb + 2 * PROJ_TILE_B + b_off + (uint32_t)(ks * 2);

            uint32_t ah[4][4], bhf[4][2], blf[4][2];
#pragma unroll
            for (int mt = 0; mt < 4; ++mt)
                LDSM_X4(ah[mt][0], ah[mt][1], ah[mt][2], ah[mt][3],
                        ab + (uint32_t)(mt * 1280));
#pragma unroll
            for (int nt = 0; nt < 4; ++nt)
                LDSM_X2(bhf[nt][0], bhf[nt][1], bb + (uint32_t)(nt * 640));
#pragma unroll
            for (int mt = 0; mt < 4; ++mt)
#pragma unroll
                for (int nt = 0; nt < 4; ++nt)
                    MMA_BF16(acc[mt][nt], ah[mt], bhf[nt]);
#pragma unroll
            for (int nt = 0; nt < 4; ++nt)
                LDSM_X2(blf[nt][0], blf[nt][1],
                        bb + (uint32_t)(PROJ_TILE_B + nt * 640));
#pragma unroll
            for (int mt = 0; mt < 4; ++mt)
#pragma unroll
                for (int nt = 0; nt < 4; ++nt)
                    MMA_BF16(acc[mt][nt], ah[mt], blf[nt]);
#pragma unroll
            for (int mt = 0; mt < 4; ++mt)
                LDSM_X4(ah[mt][0], ah[mt][1], ah[mt][2], ah[mt][3],
                        ab + (uint32_t)(PROJ_TILE_B + mt * 1280));
#pragma unroll
            for (int mt = 0; mt < 4; ++mt)
#pragma unroll
                for (int nt = 0; nt < 4; ++nt)
                    MMA_BF16(acc[mt][nt], ah[mt], bhf[nt]);
        }
        __syncthreads();
    }

    // Epilogue: bias + fp16 outputs
    const int g  = lane >> 2;
    const int t2 = (lane & 3) * 2;
    const float scale = (which == 0) ? 0.125f : 1.0f;
#pragma unroll
    for (int mt = 0; mt < 4; ++mt) {
        const int r0 = row0 + wm * 64 + mt * 16 + g;
        const int r1 = r0 + 8;
        const int bat = r0 >> 11;
        const int s0 = r0 & 2047, s1 = r1 & 2047;
#pragma unroll
        for (int nt = 0; nt < 4; ++nt) {
            const int col = col0 + wn * 32 + nt * 8 + t2;
            const float2 bv2 = *(const float2*)(bias + col);
            const int h = col >> 6, hd = col & 63;
            const int bh = bat * H_ + h;
            float v00 = (acc[mt][nt][0] + bv2.x) * scale;
            float v01 = (acc[mt][nt][1] + bv2.y) * scale;
            float v10 = (acc[mt][nt][2] + bv2.x) * scale;
            float v11 = (acc[mt][nt][3] + bv2.y) * scale;
            if (which == 0) {
                size_t o0 = ((size_t)bh * S_ + s0) * HD_ + hd;
                size_t o1 = ((size_t)bh * S_ + s1) * HD_ + hd;
                uint32_t h0 = packhf(v00, v01), h1 = packhf(v10, v11);
                float2 f0 = __half22float2(*(__half2*)&h0);
                float2 f1 = __half22float2(*(__half2*)&h1);
                *(uint32_t*)(g_qhi + o0) = h0;
                *(uint32_t*)(g_qhi + o1) = h1;
                *(uint32_t*)(g_qlo + o0) = packhf(v00 - f0.x, v01 - f0.y);
                *(uint32_t*)(g_qlo + o1) = packhf(v10 - f1.x, v11 - f1.y);
            } else if (which == 1) {
                size_t o0 = ((size_t)bh * S_ + s0) * HD_ + hd;
                size_t o1 = ((size_t)bh * S_ + s1) * HD_ + hd;
                *(uint32_t*)(g_kh + o0) = packhf(v00, v01);
                *(uint32_t*)(g_kh + o1) = packhf(v10, v11);
            } else {
                size_t base0 = ((size_t)bh * HD_ + hd) * S_;
                size_t base1 = base0 + S_;
                __half h00 = __float2half(v00), h01 = __float2half(v01);
                __half h10 = __float2half(v10), h11 = __float2half(v11);
                g_vthi[base0 + s0] = h00;
                g_vthi[base1 + s0] = h01;
                g_vthi[base0 + s1] = h10;
                g_vthi[base1 + s1] = h11;
                g_vtlo[base0 + s0] = __float2half(v00 - __half2float(h00));
                g_vtlo[base1 + s0] = __float2half(v01 - __half2float(h01));
                g_vtlo[base0 + s1] = __float2half(v10 - __half2float(h10));
                g_vtlo[base1 + s1] = __float2half(v11 - __half2float(h11));
            }
        }
    }
}

// ---------------------------------------------------------------------------
// fp16 HMMA flash attention. BR=64, BC=64, 4 warps (128 thr) -> 2 CTAs/SM.
// QK: (qhi+qlo) x Khi (4 n8-MMAs/step). PV: (Phi+Plo) x (Vhi+Vlo) minus lolo
// (6 n8-MMAs/step). Q in regs, P in regs, V pre-transposed.
// smem: 2 x {Khi 8K, Vhi 8K, Vlo 8K} + Qhi 8K + Qlo 8K = 64KB
// ---------------------------------------------------------------------------
#define ATTN_SMEM (65536 + 1024)

__global__ __launch_bounds__(128)
void attn_mma_kernel(float* __restrict__ out)
{
    extern __shared__ char asmem[];
    const uint32_t sb = (smem_u32(asmem) + 1023u) & ~1023u;

    const int tid  = threadIdx.x;
    const int lane = tid & 31, warp = tid >> 5;
    const int bh   = blockIdx.y;
    const int q0   = blockIdx.x * 64;

    const char* qh = (const char*)(g_qhi + (size_t)bh * S_ * HD_);
    const char* ql = (const char*)(g_qlo + (size_t)bh * S_ * HD_);
    const char* kh = (const char*)(g_kh  + (size_t)bh * S_ * HD_);
    const char* vh = (const char*)(g_vthi + (size_t)bh * HD_ * S_);
    const char* vl = (const char*)(g_vtlo + (size_t)bh * HD_ * S_);

    const int r8 = lane & 7;
    const int arow = ((lane >> 3) & 1) * 8 + r8;
    const int acol = lane >> 4;

    const int lrow  = tid >> 1;       // 0..63
    const int lhalf = tid & 1;        // 4-chunk halves

    // ---- stage Q tile [64][64] hi/lo ----
#pragma unroll
    for (int i = 0; i < 4; ++i) {
        int ch = lhalf * 4 + i;
        uint32_t off = SWZ(lrow * 128 + ch * 16);
        CP16(sb + 49152 + off, qh + (size_t)(q0 + lrow) * 128 + ch * 16);
        CP16(sb + 57344 + off, ql + (size_t)(q0 + lrow) * 128 + ch * 16);
    }
    CP_COMMIT();
    // ---- chunk 0 into buf0 ----
#pragma unroll
    for (int i = 0; i < 4; ++i) {
        int ch = lhalf * 4 + i;
        uint32_t off = SWZ(lrow * 128 + ch * 16);
        CP16(sb + off,         kh + (size_t)lrow * 128 + ch * 16);
        CP16(sb + 8192 + off,  vh + (size_t)lrow * (S_ * 2) + ch * 16);
        CP16(sb + 16384 + off, vl + (size_t)lrow * (S_ * 2) + ch * 16);
    }
    CP_COMMIT();
    CP_WAIT0();
    __syncthreads();

    // ---- Q fragments into registers ----
    uint32_t qa_h[4][4], qa_l[4][4];
#pragma unroll
    for (int ks = 0; ks < 4; ++ks) {
        int row = warp * 16 + arow;
        int ch  = ks * 2 + acol;
        uint32_t off = SWZ(row * 128 + ch * 16);
        LDSM_X4(qa_h[ks][0], qa_h[ks][1], qa_h[ks][2], qa_h[ks][3], sb + 49152 + off);
        LDSM_X4(qa_l[ks][0], qa_l[ks][1], qa_l[ks][2], qa_l[ks][3], sb + 57344 + off);
    }

    float m0 = -1e30f, m1 = -1e30f, l0 = 0.f, l1 = 0.f;
    float o[8][4];
#pragma unroll
    for (int nt = 0; nt < 8; ++nt)
        o[nt][0] = o[nt][1] = o[nt][2] = o[nt][3] = 0.f;

    for (int c = 0; c < 32; ++c) {
        if (c > 0) CP_WAIT0();
        __syncthreads();
        if (c + 1 < 32) {
            const uint32_t nb = sb + (uint32_t)((c + 1) & 1) * 24576;
            const int kb = (c + 1) * 64;
#pragma unroll
            for (int i = 0; i < 4; ++i) {
                int ch = lhalf * 4 + i;
                uint32_t off = SWZ(lrow * 128 + ch * 16);
                CP16(nb + off,         kh + (size_t)(kb + lrow) * 128 + ch * 16);
                CP16(nb + 8192 + off,  vh + (size_t)lrow * (S_ * 2) + kb * 2 + ch * 16);
                CP16(nb + 16384 + off, vl + (size_t)lrow * (S_ * 2) + kb * 2 + ch * 16);
            }
            CP_COMMIT();
        }
        const uint32_t buf = sb + (uint32_t)(c & 1) * 24576;

        // ---- S = Q @ Khi^T (2-term q split) ----
        float cc[8][4];
#pragma unroll
        for (int nt = 0; nt < 8; ++nt)
            cc[nt][0] = cc[nt][1] = cc[nt][2] = cc[nt][3] = 0.f;

#pragma unroll
        for (int ks = 0; ks < 4; ++ks) {
#pragma unroll
            for (int np = 0; np < 4; ++np) {
                int row = np * 16 + arow;
                int ch  = ks * 2 + acol;
                uint32_t off = SWZ(row * 128 + ch * 16);
                uint32_t b0, b1, b2, b3;
                LDSM_X4(b0, b1, b2, b3, buf + off);
                MMA_F16S(cc[2 * np],     qa_h[ks], b0, b2);
                MMA_F16S(cc[2 * np + 1], qa_h[ks], b1, b3);
                MMA_F16S(cc[2 * np],     qa_l[ks], b0, b2);
                MMA_F16S(cc[2 * np + 1], qa_l[ks], b1, b3);
            }
        }

        // ---- online softmax ----
        float rmx0 = cc[0][0], rmx1 = cc[0][2];
#pragma unroll
        for (int nt = 0; nt < 8; ++nt) {
            rmx0 = fmaxf(rmx0, fmaxf(cc[nt][0], cc[nt][1]));
            rmx1 = fmaxf(rmx1, fmaxf(cc[nt][2], cc[nt][3]));
        }
        rmx0 = fmaxf(rmx0, __shfl_xor_sync(0xffffffffu, rmx0, 1));
        rmx0 = fmaxf(rmx0, __shfl_xor_sync(0xffffffffu, rmx0, 2));
        rmx1 = fmaxf(rmx1, __shfl_xor_sync(0xffffffffu, rmx1, 1));
        rmx1 = fmaxf(rmx1, __shfl_xor_sync(0xffffffffu, rmx1, 2));
        float mn0 = fmaxf(m0, rmx0), mn1 = fmaxf(m1, rmx1);
        float cr0 = fexp(m0 - mn0), cr1 = fexp(m1 - mn1);
        m0 = mn0; m1 = mn1;
        float rs0 = 0.f, rs1 = 0.f;
#pragma unroll
        for (int nt = 0; nt < 8; ++nt) {
            cc[nt][0] = fexp(cc[nt][0] - mn0);
            cc[nt][1] = fexp(cc[nt][1] - mn0);
            cc[nt][2] = fexp(cc[nt][2] - mn1);
            cc[nt][3] = fexp(cc[nt][3] - mn1);
            rs0 += cc[nt][0] + cc[nt][1];
            rs1 += cc[nt][2] + cc[nt][3];
        }
        rs0 += __shfl_xor_sync(0xffffffffu, rs0, 1);
        rs0 += __shfl_xor_sync(0xffffffffu, rs0, 2);
        rs1 += __shfl_xor_sync(0xffffffffu, rs1, 1);
        rs1 += __shfl_xor_sync(0xffffffffu, rs1, 2);
        l0 = l0 * cr0 + rs0;
        l1 = l1 * cr1 + rs1;
#pragma unroll
        for (int nt = 0; nt < 8; ++nt) {
            o[nt][0] *= cr0; o[nt][1] *= cr0;
            o[nt][2] *= cr1; o[nt][3] *= cr1;
        }

        // ---- pack P into fp16 A fragments (hi/lo) ----
        uint32_t pa_h[4][4], pa_l[4][4];
#pragma unroll
        for (int j = 0; j < 4; ++j) {
            float x0 = cc[2 * j][0],     x1 = cc[2 * j][1];
            float x2 = cc[2 * j][2],     x3 = cc[2 * j][3];
            float x4 = cc[2 * j + 1][0], x5 = cc[2 * j + 1][1];
            float x6 = cc[2 * j + 1][2], x7 = cc[2 * j + 1][3];
            uint32_t h0 = packhf(x0, x1), h1 = packhf(x2, x3);
            uint32_t h2 = packhf(x4, x5), h3 = packhf(x6, x7);
            pa_h[j][0] = h0; pa_h[j][1] = h1; pa_h[j][2] = h2; pa_h[j][3] = h3;
            float2 f0 = __half22float2(*(__half2*)&h0);
            float2 f1 = __half22float2(*(__half2*)&h1);
            float2 f2 = __half22float2(*(__half2*)&h2);
            float2 f3 = __half22float2(*(__half2*)&h3);
            pa_l[j][0] = packhf(x0 - f0.x, x1 - f0.y);
            pa_l[j][1] = packhf(x2 - f1.x, x3 - f1.y);
            pa_l[j][2] = packhf(x4 - f2.x, x5 - f2.y);
            pa_l[j][3] = packhf(x6 - f3.x, x7 - f3.y);
        }

        // ---- O += P @ V (3-term split) ----
#pragma unroll
        for (int j = 0; j < 4; ++j) {
#pragma unroll
            for (int np = 0; np < 4; ++np) {
                int row = np * 16 + arow;
                int ch  = j * 2 + acol;
                uint32_t off = SWZ(row * 128 + ch * 16);
                uint32_t b0, b1, b2, b3;
                LDSM_X4(b0, b1, b2, b3, buf + 8192 + off);     // V hi
                MMA_F16S(o[2 * np],     pa_h[j], b0, b2);
                MMA_F16S(o[2 * np + 1], pa_h[j], b1, b3);
                MMA_F16S(o[2 * np],     pa_l[j], b0, b2);
                MMA_F16S(o[2 * np + 1], pa_l[j], b1, b3);
                LDSM_X4(b0, b1, b2, b3, buf + 16384 + off);    // V lo
                MMA_F16S(o[2 * np],     pa_h[j], b0, b2);
                MMA_F16S(o[2 * np + 1], pa_h[j], b1, b3);
            }
        }
    }

    // ---- epilogue ----
    const int g  = lane >> 2;
    const int t2 = (lane & 3) * 2;
    const int bat = bh >> 4, h = bh & 15;
    const int s0 = q0 + warp * 16 + g, s1 = s0 + 8;
    const float inv0 = 1.0f / l0, inv1 = 1.0f / l1;
#pragma unroll
    for (int nt = 0; nt < 8; ++nt) {
        int col = h * HD_ + nt * 8 + t2;
        float2 v0, v1;
        v0.x = o[nt][0] * inv0; v0.y = o[nt][1] * inv0;
        v1.x = o[nt][2] * inv1; v1.y = o[nt][3] * inv1;
        *(float2*)(out + ((size_t)bat * S_ + s0) * DM + col) = v0;
        *(float2*)(out + ((size_t)bat * S_ + s1) * DM + col) = v1;
    }
}

// ---------------------------------------------------------------------------
extern "C" void kernel_launch(void* const* d_in, const int* in_sizes, int n_in,
                              void* d_out, int out_size)
{
    (void)in_sizes; (void)n_in; (void)out_size;
    const float* Q  = (const float*)d_in[0];
    const float* V  = (const float*)d_in[1];
    const float* K  = (const float*)d_in[2];
    const float* wq = (const float*)d_in[3];
    const float* bq = (const float*)d_in[4];
    const float* wk = (const float*)d_in[5];
    const float* bk = (const float*)d_in[6];
    const float* wv = (const float*)d_in[7];
    const float* bv = (const float*)d_in[8];
    float* out = (float*)d_out;

    dim3 xg((MX * DIN) / 4 / 256, 3);
    conv_x_kernel<<<xg, 256>>>(Q, K, V);
    dim3 wg(DM / 32, DIN / 32, 3);
    conv_w_kernel<<<wg, 256>>>(wq, wk, wv);

    cudaFuncSetAttribute(proj_mma_kernel, cudaFuncAttributeMaxDynamicSharedMemorySize, PROJ_SMEM);
    dim3 pg(DM / 128, MX / 128, 3);
    proj_mma_kernel<<<pg, 256, PROJ_SMEM>>>(bq, bk, bv);

    cudaFuncSetAttribute(attn_mma_kernel, cudaFuncAttributeMaxDynamicSharedMemorySize, ATTN_SMEM);
    dim3 ag(S_ / 64, B_ * H_);
    attn_mma_kernel<<<ag, 128, ATTN_SMEM>>>(out);
}

// round 7
// speedup vs baseline: 1.6430x; 1.6430x over previous
#include <cuda_runtime.h>
#include <cuda_bf16.h>
#include <cuda_fp16.h>
#include <cstdint>

#define B_   4
#define S_   2048
#define DIN  1024
#define DM   1024
#define H_   16
#define HD_  64
#define MX   (B_ * S_)   // 8192

// ---------------- scratch (static device arrays: no allocs) ----------------
__device__ __nv_bfloat16 g_xhi[3][(size_t)MX * DIN];
__device__ __nv_bfloat16 g_xlo[3][(size_t)MX * DIN];
__device__ __nv_bfloat16 g_whi[3][(size_t)DM * DIN];
__device__ __nv_bfloat16 g_wlo[3][(size_t)DM * DIN];
// projected tensors (fp16). q: hi (pre-scaled), k: hi, v: transposed hi
__device__ __half g_qh [(size_t)64 * S_ * HD_];
__device__ __half g_kh [(size_t)64 * S_ * HD_];
__device__ __half g_vth[(size_t)64 * HD_ * S_];

// ---------------- PTX helpers (baseline sm_80-class ISA only) --------------
__device__ __forceinline__ uint32_t smem_u32(const void* p) {
    uint32_t a;
    asm("{ .reg .u64 t; cvta.to.shared.u64 t, %1; cvt.u32.u64 %0, t; }"
        : "=r"(a) : "l"(p));
    return a;
}

#define CP16(dst, src) \
    asm volatile("cp.async.cg.shared.global [%0], [%1], 16;" \
                 :: "r"(dst), "l"(src) : "memory")
#define CP_COMMIT() asm volatile("cp.async.commit_group;" ::: "memory")
#define CP_WAIT1()  asm volatile("cp.async.wait_group 1;" ::: "memory")
#define CP_WAIT0()  asm volatile("cp.async.wait_group 0;" ::: "memory")

#define LDSM_X4(r0, r1, r2, r3, a) \
    asm volatile("ldmatrix.sync.aligned.m8n8.x4.shared.b16 {%0,%1,%2,%3}, [%4];" \
                 : "=r"(r0), "=r"(r1), "=r"(r2), "=r"(r3) : "r"(a))
#define LDSM_X2(r0, r1, a) \
    asm volatile("ldmatrix.sync.aligned.m8n8.x2.shared.b16 {%0,%1}, [%2];" \
                 : "=r"(r0), "=r"(r1) : "r"(a))

#define MMA_BF16(c, a, b) \
    asm volatile("mma.sync.aligned.m16n8k16.row.col.f32.bf16.bf16.f32 " \
                 "{%0,%1,%2,%3}, {%4,%5,%6,%7}, {%8,%9}, {%0,%1,%2,%3};" \
                 : "+f"((c)[0]), "+f"((c)[1]), "+f"((c)[2]), "+f"((c)[3]) \
                 : "r"((a)[0]), "r"((a)[1]), "r"((a)[2]), "r"((a)[3]), \
                   "r"((b)[0]), "r"((b)[1]))
#define MMA_F16S(c, a, b0v, b1v) \
    asm volatile("mma.sync.aligned.m16n8k16.row.col.f32.f16.f16.f32 " \
                 "{%0,%1,%2,%3}, {%4,%5,%6,%7}, {%8,%9}, {%0,%1,%2,%3};" \
                 : "+f"((c)[0]), "+f"((c)[1]), "+f"((c)[2]), "+f"((c)[3]) \
                 : "r"((a)[0]), "r"((a)[1]), "r"((a)[2]), "r"((a)[3]), \
                   "r"(b0v), "r"(b1v))

#define SWZ(x) ((uint32_t)(x) ^ ((((uint32_t)(x)) >> 3) & 0x70))

// fast e^x on the FMA pipe
__device__ __forceinline__ float fexp(float x) {
    float y = x * 1.44269504f;
    y = fmaxf(y, -100.f);
    float t = y + 12582912.0f;
    float nf = t - 12582912.0f;
    float f = y - nf;
    uint32_t sc = (__float_as_uint(t) << 23) + 0x3F800000u;
    float p = fmaf(f, 0.0096181291f, 0.0555041087f);
    p = fmaf(f, p, 0.2402265069f);
    p = fmaf(f, p, 0.6931471806f);
    p = fmaf(f, p, 1.0f);
    return p * __uint_as_float(sc);
}

__device__ __forceinline__ uint32_t packhf(float x, float y) {
    __half2 h = __floats2half2_rn(x, y);
    return *(uint32_t*)&h;
}

// ---------------------------------------------------------------------------
// fp32 -> bf16 hi/lo split for X inputs. blockIdx.y selects slot.
// ---------------------------------------------------------------------------
__global__ __launch_bounds__(256)
void conv_x_kernel(const float* __restrict__ Q, const float* __restrict__ K,
                   const float* __restrict__ V)
{
    const int slot = blockIdx.y;
    const float* X = (slot == 0) ? Q : (slot == 1) ? K : V;
    size_t i = (size_t)blockIdx.x * 256 + threadIdx.x;
    float4 v = ((const float4*)X)[i];
    __nv_bfloat16 h0 = __float2bfloat16(v.x), h1 = __float2bfloat16(v.y);
    __nv_bfloat16 h2 = __float2bfloat16(v.z), h3 = __float2bfloat16(v.w);
    __nv_bfloat16 l0 = __float2bfloat16(v.x - __bfloat162float(h0));
    __nv_bfloat16 l1 = __float2bfloat16(v.y - __bfloat162float(h1));
    __nv_bfloat16 l2 = __float2bfloat16(v.z - __bfloat162float(h2));
    __nv_bfloat16 l3 = __float2bfloat16(v.w - __bfloat162float(h3));
    __nv_bfloat162* hp = reinterpret_cast<__nv_bfloat162*>(g_xhi[slot] + i * 4);
    __nv_bfloat162* lp = reinterpret_cast<__nv_bfloat162*>(g_xlo[slot] + i * 4);
    __nv_bfloat162 a; a.x = h0; a.y = h1; hp[0] = a;
    __nv_bfloat162 b; b.x = h2; b.y = h3; hp[1] = b;
    __nv_bfloat162 c; c.x = l0; c.y = l1; lp[0] = c;
    __nv_bfloat162 d; d.x = l2; d.y = l3; lp[1] = d;
}

// ---------------------------------------------------------------------------
// W [K][N] fp32 -> transposed [N][K] bf16 hi/lo. blockIdx.z selects slot.
// ---------------------------------------------------------------------------
__global__ __launch_bounds__(256)
void conv_w_kernel(const float* __restrict__ WQ, const float* __restrict__ WK,
                   const float* __restrict__ WV)
{
    __shared__ float t[32][33];
    const int slot = blockIdx.z;
    const float* W = (slot == 0) ? WQ : (slot == 1) ? WK : WV;
    const int n0 = blockIdx.x * 32, k0 = blockIdx.y * 32;
    const int tx = threadIdx.x & 31, ty = threadIdx.x >> 5;
#pragma unroll
    for (int r = 0; r < 32; r += 8)
        t[ty + r][tx] = W[(size_t)(k0 + ty + r) * DM + n0 + tx];
    __syncthreads();
#pragma unroll
    for (int r = 0; r < 32; r += 8) {
        int n = ty + r;
        float x = t[tx][n];
        __nv_bfloat16 h = __float2bfloat16(x);
        float l = x - __bfloat162float(h);
        size_t o = (size_t)(n0 + n) * DIN + k0 + tx;
        g_whi[slot][o] = h;
        g_wlo[slot][o] = __float2bfloat16(l);
    }
}

// ---------------------------------------------------------------------------
// HMMA projection GEMM (bf16 3-term split). One launch per `which`:
// which==0: q*0.125 -> g_qh [bh][s][hd]
// which==1: k       -> g_kh [bh][s][hd]
// which==2: v       -> g_vth transposed [bh][hd][s]
// ---------------------------------------------------------------------------
#define PROJ_TILE_B   10240
#define PROJ_BUF_B    (4 * PROJ_TILE_B)
#define PROJ_SMEM     (2 * PROJ_BUF_B)

__global__ __launch_bounds__(256)
void proj_mma_kernel(const float* __restrict__ bias, int which)
{
    extern __shared__ char dsm[];
    const uint32_t sbase = smem_u32(dsm);

    const __nv_bfloat16* Ah = g_xhi[which];
    const __nv_bfloat16* Al = g_xlo[which];
    const __nv_bfloat16* Bh = g_whi[which];
    const __nv_bfloat16* Bl = g_wlo[which];

    const int tid  = threadIdx.x;
    const int wid  = tid >> 5, lane = tid & 31;
    const int wm   = wid & 1;
    const int wn   = wid >> 1;
    const int row0 = blockIdx.y * 128, col0 = blockIdx.x * 128;

    const int lrow  = tid >> 1;
    const int lhalf = tid & 1;
    const uint32_t sdst = (uint32_t)(lrow * 80 + lhalf * 32);
    const char* gA_h = (const char*)(Ah + (size_t)(row0 + lrow) * DIN) + lhalf * 32;
    const char* gA_l = (const char*)(Al + (size_t)(row0 + lrow) * DIN) + lhalf * 32;
    const char* gB_h = (const char*)(Bh + (size_t)(col0 + lrow) * DIN) + lhalf * 32;
    const char* gB_l = (const char*)(Bl + (size_t)(col0 + lrow) * DIN) + lhalf * 32;

    const int r8 = lane & 7;
    const int ami = lane >> 3;
    const uint32_t a_off = (uint32_t)(((wm * 64 + (ami & 1) * 8 + r8) * 40
                                       + (ami >> 1) * 8) * 2);
    const int bmi = (lane >> 3) & 1;
    const uint32_t b_off = (uint32_t)(((wn * 32 + r8) * 40 + bmi * 8) * 2);

    float acc[4][4][4];
#pragma unroll
    for (int i = 0; i < 4; ++i)
#pragma unroll
        for (int j = 0; j < 4; ++j)
            acc[i][j][0] = acc[i][j][1] = acc[i][j][2] = acc[i][j][3] = 0.f;

    {
        uint32_t b0 = sbase;
        CP16(b0 + sdst,                    gA_h);
        CP16(b0 + sdst + 16,               gA_h + 16);
        CP16(b0 + PROJ_TILE_B + sdst,      gA_l);
        CP16(b0 + PROJ_TILE_B + sdst + 16, gA_l + 16);
        CP16(b0 + 2 * PROJ_TILE_B + sdst,      gB_h);
        CP16(b0 + 2 * PROJ_TILE_B + sdst + 16, gB_h + 16);
        CP16(b0 + 3 * PROJ_TILE_B + sdst,      gB_l);
        CP16(b0 + 3 * PROJ_TILE_B + sdst + 16, gB_l + 16);
        CP_COMMIT();
    }

    for (int c = 0; c < 32; ++c) {
        const uint32_t bufb = sbase + (uint32_t)(c & 1) * PROJ_BUF_B;
        if (c + 1 < 32) {
            const uint32_t nb = sbase + (uint32_t)((c + 1) & 1) * PROJ_BUF_B;
            const int kb = (c + 1) * 64;
            CP16(nb + sdst,                    gA_h + kb);
            CP16(nb + sdst + 16,               gA_h + kb + 16);
            CP16(nb + PROJ_TILE_B + sdst,      gA_l + kb);
            CP16(nb + PROJ_TILE_B + sdst + 16, gA_l + kb + 16);
            CP16(nb + 2 * PROJ_TILE_B + sdst,      gB_h + kb);
            CP16(nb + 2 * PROJ_TILE_B + sdst + 16, gB_h + kb + 16);
            CP16(nb + 3 * PROJ_TILE_B + sdst,      gB_l + kb);
            CP16(nb + 3 * PROJ_TILE_B + sdst + 16, gB_l + kb + 16);
            CP_COMMIT();
            CP_WAIT1();
        } else {
            CP_WAIT0();
        }
        __syncthreads();

#pragma unroll
        for (int ks = 0; ks < 32; ks += 16) {
            const uint32_t ab = bufb + a_off + (uint32_t)(ks * 2);
            const uint32_t bb = bufb + 2 * PROJ_TILE_B + b_off + (uint32_t)(ks * 2);

            uint32_t ah[4][4], bhf[4][2], blf[4][2];
#pragma unroll
            for (int mt = 0; mt < 4; ++mt)
                LDSM_X4(ah[mt][0], ah[mt][1], ah[mt][2], ah[mt][3],
                        ab + (uint32_t)(mt * 1280));
#pragma unroll
            for (int nt = 0; nt < 4; ++nt)
                LDSM_X2(bhf[nt][0], bhf[nt][1], bb + (uint32_t)(nt * 640));
#pragma unroll
            for (int mt = 0; mt < 4; ++mt)
#pragma unroll
                for (int nt = 0; nt < 4; ++nt)
                    MMA_BF16(acc[mt][nt], ah[mt], bhf[nt]);
#pragma unroll
            for (int nt = 0; nt < 4; ++nt)
                LDSM_X2(blf[nt][0], blf[nt][1],
                        bb + (uint32_t)(PROJ_TILE_B + nt * 640));
#pragma unroll
            for (int mt = 0; mt < 4; ++mt)
#pragma unroll
                for (int nt = 0; nt < 4; ++nt)
                    MMA_BF16(acc[mt][nt], ah[mt], blf[nt]);
#pragma unroll
            for (int mt = 0; mt < 4; ++mt)
                LDSM_X4(ah[mt][0], ah[mt][1], ah[mt][2], ah[mt][3],
                        ab + (uint32_t)(PROJ_TILE_B + mt * 1280));
#pragma unroll
            for (int mt = 0; mt < 4; ++mt)
#pragma unroll
                for (int nt = 0; nt < 4; ++nt)
                    MMA_BF16(acc[mt][nt], ah[mt], bhf[nt]);
        }
        __syncthreads();
    }

    // Epilogue: bias + fp16 outputs (hi only)
    const int g  = lane >> 2;
    const int t2 = (lane & 3) * 2;
    const float scale = (which == 0) ? 0.125f : 1.0f;
#pragma unroll
    for (int mt = 0; mt < 4; ++mt) {
        const int r0 = row0 + wm * 64 + mt * 16 + g;
        const int r1 = r0 + 8;
        const int bat = r0 >> 11;
        const int s0 = r0 & 2047, s1 = r1 & 2047;
#pragma unroll
        for (int nt = 0; nt < 4; ++nt) {
            const int col = col0 + wn * 32 + nt * 8 + t2;
            const float2 bv2 = *(const float2*)(bias + col);
            const int h = col >> 6, hd = col & 63;
            const int bh = bat * H_ + h;
            float v00 = (acc[mt][nt][0] + bv2.x) * scale;
            float v01 = (acc[mt][nt][1] + bv2.y) * scale;
            float v10 = (acc[mt][nt][2] + bv2.x) * scale;
            float v11 = (acc[mt][nt][3] + bv2.y) * scale;
            if (which < 2) {
                __half* dst = (which == 0) ? g_qh : g_kh;
                size_t o0 = ((size_t)bh * S_ + s0) * HD_ + hd;
                size_t o1 = ((size_t)bh * S_ + s1) * HD_ + hd;
                *(uint32_t*)(dst + o0) = packhf(v00, v01);
                *(uint32_t*)(dst + o1) = packhf(v10, v11);
            } else {
                size_t base0 = ((size_t)bh * HD_ + hd) * S_;
                size_t base1 = base0 + S_;
                g_vth[base0 + s0] = __float2half(v00);
                g_vth[base1 + s0] = __float2half(v01);
                g_vth[base0 + s1] = __float2half(v10);
                g_vth[base1 + s1] = __float2half(v11);
            }
        }
    }
}

// ---------------------------------------------------------------------------
// fp16 HMMA flash attention. BR=64, BC=64, 4 warps, 4 CTAs/SM target.
// QK: qh x Kh (2 n8-MMAs/step). PV: (Ph+Pl) x Vh (4 n8-MMAs/step).
// smem: Q 8K @32768, double-buffered {Kh 8K, Vh 8K} @0/@16384 = 40KB
// ---------------------------------------------------------------------------
#define ATTN_SMEM (40960 + 1024)

__global__ __launch_bounds__(128, 4)
void attn_mma_kernel(float* __restrict__ out)
{
    extern __shared__ char asmem[];
    const uint32_t sb = (smem_u32(asmem) + 1023u) & ~1023u;

    const int tid  = threadIdx.x;
    const int lane = tid & 31, warp = tid >> 5;
    const int bh   = blockIdx.y;
    const int q0   = blockIdx.x * 64;

    const char* qh = (const char*)(g_qh  + (size_t)bh * S_ * HD_);
    const char* kh = (const char*)(g_kh  + (size_t)bh * S_ * HD_);
    const char* vh = (const char*)(g_vth + (size_t)bh * HD_ * S_);

    const int r8 = lane & 7;
    const int arow = ((lane >> 3) & 1) * 8 + r8;
    const int acol = lane >> 4;

    const int lrow  = tid >> 1;       // 0..63
    const int lhalf = tid & 1;

    // ---- stage Q tile [64][64] ----
#pragma unroll
    for (int i = 0; i < 4; ++i) {
        int ch = lhalf * 4 + i;
        uint32_t off = SWZ(lrow * 128 + ch * 16);
        CP16(sb + 32768 + off, qh + (size_t)(q0 + lrow) * 128 + ch * 16);
    }
    CP_COMMIT();
    // ---- chunk 0 into buf0 ----
#pragma unroll
    for (int i = 0; i < 4; ++i) {
        int ch = lhalf * 4 + i;
        uint32_t off = SWZ(lrow * 128 + ch * 16);
        CP16(sb + off,        kh + (size_t)lrow * 128 + ch * 16);
        CP16(sb + 8192 + off, vh + (size_t)lrow * (S_ * 2) + ch * 16);
    }
    CP_COMMIT();
    CP_WAIT0();
    __syncthreads();

    // ---- Q fragments into registers ----
    uint32_t qa_h[4][4];
#pragma unroll
    for (int ks = 0; ks < 4; ++ks) {
        int row = warp * 16 + arow;
        int ch  = ks * 2 + acol;
        uint32_t off = SWZ(row * 128 + ch * 16);
        LDSM_X4(qa_h[ks][0], qa_h[ks][1], qa_h[ks][2], qa_h[ks][3], sb + 32768 + off);
    }

    float m0 = -1e30f, m1 = -1e30f, l0 = 0.f, l1 = 0.f;
    float o[8][4];
#pragma unroll
    for (int nt = 0; nt < 8; ++nt)
        o[nt][0] = o[nt][1] = o[nt][2] = o[nt][3] = 0.f;

    for (int c = 0; c < 32; ++c) {
        if (c > 0) CP_WAIT0();
        __syncthreads();
        if (c + 1 < 32) {
            const uint32_t nb = sb + (uint32_t)((c + 1) & 1) * 16384;
            const int kb = (c + 1) * 64;
#pragma unroll
            for (int i = 0; i < 4; ++i) {
                int ch = lhalf * 4 + i;
                uint32_t off = SWZ(lrow * 128 + ch * 16);
                CP16(nb + off,        kh + (size_t)(kb + lrow) * 128 + ch * 16);
                CP16(nb + 8192 + off, vh + (size_t)lrow * (S_ * 2) + kb * 2 + ch * 16);
            }
            CP_COMMIT();
        }
        const uint32_t buf = sb + (uint32_t)(c & 1) * 16384;

        // ---- S = qh @ Kh^T ----
        float cc[8][4];
#pragma unroll
        for (int nt = 0; nt < 8; ++nt)
            cc[nt][0] = cc[nt][1] = cc[nt][2] = cc[nt][3] = 0.f;

#pragma unroll
        for (int ks = 0; ks < 4; ++ks) {
#pragma unroll
            for (int np = 0; np < 4; ++np) {
                uint32_t off = SWZ((np * 16 + arow) * 128 + (ks * 2 + acol) * 16);
                uint32_t b0, b1, b2, b3;
                LDSM_X4(b0, b1, b2, b3, buf + off);
                MMA_F16S(cc[2 * np],     qa_h[ks], b0, b2);
                MMA_F16S(cc[2 * np + 1], qa_h[ks], b1, b3);
            }
        }

        // ---- online softmax ----
        float rmx0 = cc[0][0], rmx1 = cc[0][2];
#pragma unroll
        for (int nt = 0; nt < 8; ++nt) {
            rmx0 = fmaxf(rmx0, fmaxf(cc[nt][0], cc[nt][1]));
            rmx1 = fmaxf(rmx1, fmaxf(cc[nt][2], cc[nt][3]));
        }
        rmx0 = fmaxf(rmx0, __shfl_xor_sync(0xffffffffu, rmx0, 1));
        rmx0 = fmaxf(rmx0, __shfl_xor_sync(0xffffffffu, rmx0, 2));
        rmx1 = fmaxf(rmx1, __shfl_xor_sync(0xffffffffu, rmx1, 1));
        rmx1 = fmaxf(rmx1, __shfl_xor_sync(0xffffffffu, rmx1, 2));
        float mn0 = fmaxf(m0, rmx0), mn1 = fmaxf(m1, rmx1);
        float cr0 = fexp(m0 - mn0), cr1 = fexp(m1 - mn1);
        m0 = mn0; m1 = mn1;
        float rs0 = 0.f, rs1 = 0.f;
#pragma unroll
        for (int nt = 0; nt < 8; ++nt) {
            cc[nt][0] = fexp(cc[nt][0] - mn0);
            cc[nt][1] = fexp(cc[nt][1] - mn0);
            cc[nt][2] = fexp(cc[nt][2] - mn1);
            cc[nt][3] = fexp(cc[nt][3] - mn1);
            rs0 += cc[nt][0] + cc[nt][1];
            rs1 += cc[nt][2] + cc[nt][3];
        }
        rs0 += __shfl_xor_sync(0xffffffffu, rs0, 1);
        rs0 += __shfl_xor_sync(0xffffffffu, rs0, 2);
        rs1 += __shfl_xor_sync(0xffffffffu, rs1, 1);
        rs1 += __shfl_xor_sync(0xffffffffu, rs1, 2);
        l0 = l0 * cr0 + rs0;
        l1 = l1 * cr1 + rs1;
#pragma unroll
        for (int nt = 0; nt < 8; ++nt) {
            o[nt][0] *= cr0; o[nt][1] *= cr0;
            o[nt][2] *= cr1; o[nt][3] *= cr1;
        }

        // ---- pack P into fp16 A fragments (hi/lo) ----
        uint32_t pa_h[4][4], pa_l[4][4];
#pragma unroll
        for (int j = 0; j < 4; ++j) {
            float x0 = cc[2 * j][0],     x1 = cc[2 * j][1];
            float x2 = cc[2 * j][2],     x3 = cc[2 * j][3];
            float x4 = cc[2 * j + 1][0], x5 = cc[2 * j + 1][1];
            float x6 = cc[2 * j + 1][2], x7 = cc[2 * j + 1][3];
            uint32_t h0 = packhf(x0, x1), h1 = packhf(x2, x3);
            uint32_t h2 = packhf(x4, x5), h3 = packhf(x6, x7);
            pa_h[j][0] = h0; pa_h[j][1] = h1; pa_h[j][2] = h2; pa_h[j][3] = h3;
            float2 f0 = __half22float2(*(__half2*)&h0);
            float2 f1 = __half22float2(*(__half2*)&h1);
            float2 f2 = __half22float2(*(__half2*)&h2);
            float2 f3 = __half22float2(*(__half2*)&h3);
            pa_l[j][0] = packhf(x0 - f0.x, x1 - f0.y);
            pa_l[j][1] = packhf(x2 - f1.x, x3 - f1.y);
            pa_l[j][2] = packhf(x4 - f2.x, x5 - f2.y);
            pa_l[j][3] = packhf(x6 - f3.x, x7 - f3.y);
        }

        // ---- O += (Ph + Pl) @ Vh ----
#pragma unroll
        for (int j = 0; j < 4; ++j) {
#pragma unroll
            for (int np = 0; np < 4; ++np) {
                uint32_t off = SWZ((np * 16 + arow) * 128 + (j * 2 + acol) * 16);
                uint32_t b0, b1, b2, b3;
                LDSM_X4(b0, b1, b2, b3, buf + 8192 + off);
                MMA_F16S(o[2 * np],     pa_h[j], b0, b2);
                MMA_F16S(o[2 * np + 1], pa_h[j], b1, b3);
                MMA_F16S(o[2 * np],     pa_l[j], b0, b2);
                MMA_F16S(o[2 * np + 1], pa_l[j], b1, b3);
            }
        }
    }

    // ---- epilogue ----
    const int g  = lane >> 2;
    const int t2 = (lane & 3) * 2;
    const int bat = bh >> 4, h = bh & 15;
    const int s0 = q0 + warp * 16 + g, s1 = s0 + 8;
    const float inv0 = 1.0f / l0, inv1 = 1.0f / l1;
#pragma unroll
    for (int nt = 0; nt < 8; ++nt) {
        int col = h * HD_ + nt * 8 + t2;
        float2 v0, v1;
        v0.x = o[nt][0] * inv0; v0.y = o[nt][1] * inv0;
        v1.x = o[nt][2] * inv1; v1.y = o[nt][3] * inv1;
        *(float2*)(out + ((size_t)bat * S_ + s0) * DM + col) = v0;
        *(float2*)(out + ((size_t)bat * S_ + s1) * DM + col) = v1;
    }
}

// ---------------------------------------------------------------------------
extern "C" void kernel_launch(void* const* d_in, const int* in_sizes, int n_in,
                              void* d_out, int out_size)
{
    (void)in_sizes; (void)n_in; (void)out_size;
    const float* Q  = (const float*)d_in[0];
    const float* V  = (const float*)d_in[1];
    const float* K  = (const float*)d_in[2];
    const float* wq = (const float*)d_in[3];
    const float* bq = (const float*)d_in[4];
    const float* wk = (const float*)d_in[5];
    const float* bk = (const float*)d_in[6];
    const float* wv = (const float*)d_in[7];
    const float* bv = (const float*)d_in[8];
    float* out = (float*)d_out;

    dim3 xg((MX * DIN) / 4 / 256, 3);
    conv_x_kernel<<<xg, 256>>>(Q, K, V);
    dim3 wg(DM / 32, DIN / 32, 3);
    conv_w_kernel<<<wg, 256>>>(wq, wk, wv);

    // projections: separate launches (R4-measured-good structure)
    cudaFuncSetAttribute(proj_mma_kernel, cudaFuncAttributeMaxDynamicSharedMemorySize, PROJ_SMEM);
    dim3 pg(DM / 128, MX / 128);
    proj_mma_kernel<<<pg, 256, PROJ_SMEM>>>(bq, 0);
    proj_mma_kernel<<<pg, 256, PROJ_SMEM>>>(bk, 1);
    proj_mma_kernel<<<pg, 256, PROJ_SMEM>>>(bv, 2);

    cudaFuncSetAttribute(attn_mma_kernel, cudaFuncAttributeMaxDynamicSharedMemorySize, ATTN_SMEM);
    dim3 ag(S_ / 64, B_ * H_);
    attn_mma_kernel<<<ag, 128, ATTN_SMEM>>>(out);
}

// round 8
// speedup vs baseline: 1.8279x; 1.1126x over previous
#include <cuda_runtime.h>
#include <cuda_bf16.h>
#include <cuda_fp16.h>
#include <cstdint>

#define B_   4
#define S_   2048
#define DIN  1024
#define DM   1024
#define H_   16
#define HD_  64
#define MX   (B_ * S_)   // 8192

// ---------------- scratch (static device arrays: no allocs) ----------------
__device__ __nv_bfloat16 g_xhi[3][(size_t)MX * DIN];
__device__ __nv_bfloat16 g_xlo[3][(size_t)MX * DIN];
__device__ __nv_bfloat16 g_whi[3][(size_t)DM * DIN];
__device__ __nv_bfloat16 g_wlo[3][(size_t)DM * DIN];
// projected tensors (fp16), all [bh][s][hd]: q pre-scaled by 0.125
__device__ __half g_qh[(size_t)64 * S_ * HD_];
__device__ __half g_kh[(size_t)64 * S_ * HD_];
__device__ __half g_vh[(size_t)64 * S_ * HD_];

// ---------------- PTX helpers (baseline sm_80-class ISA only) --------------
__device__ __forceinline__ uint32_t smem_u32(const void* p) {
    uint32_t a;
    asm("{ .reg .u64 t; cvta.to.shared.u64 t, %1; cvt.u32.u64 %0, t; }"
        : "=r"(a) : "l"(p));
    return a;
}

#define CP16(dst, src) \
    asm volatile("cp.async.cg.shared.global [%0], [%1], 16;" \
                 :: "r"(dst), "l"(src) : "memory")
#define CP_COMMIT() asm volatile("cp.async.commit_group;" ::: "memory")
#define CP_WAIT1()  asm volatile("cp.async.wait_group 1;" ::: "memory")
#define CP_WAIT0()  asm volatile("cp.async.wait_group 0;" ::: "memory")

#define LDSM_X4(r0, r1, r2, r3, a) \
    asm volatile("ldmatrix.sync.aligned.m8n8.x4.shared.b16 {%0,%1,%2,%3}, [%4];" \
                 : "=r"(r0), "=r"(r1), "=r"(r2), "=r"(r3) : "r"(a))
#define LDSM_X4T(r0, r1, r2, r3, a) \
    asm volatile("ldmatrix.sync.aligned.m8n8.x4.trans.shared.b16 {%0,%1,%2,%3}, [%4];" \
                 : "=r"(r0), "=r"(r1), "=r"(r2), "=r"(r3) : "r"(a))
#define LDSM_X2(r0, r1, a) \
    asm volatile("ldmatrix.sync.aligned.m8n8.x2.shared.b16 {%0,%1}, [%2];" \
                 : "=r"(r0), "=r"(r1) : "r"(a))

#define MMA_BF16(c, a, b) \
    asm volatile("mma.sync.aligned.m16n8k16.row.col.f32.bf16.bf16.f32 " \
                 "{%0,%1,%2,%3}, {%4,%5,%6,%7}, {%8,%9}, {%0,%1,%2,%3};" \
                 : "+f"((c)[0]), "+f"((c)[1]), "+f"((c)[2]), "+f"((c)[3]) \
                 : "r"((a)[0]), "r"((a)[1]), "r"((a)[2]), "r"((a)[3]), \
                   "r"((b)[0]), "r"((b)[1]))
#define MMA_F16S(c, a, b0v, b1v) \
    asm volatile("mma.sync.aligned.m16n8k16.row.col.f32.f16.f16.f32 " \
                 "{%0,%1,%2,%3}, {%4,%5,%6,%7}, {%8,%9}, {%0,%1,%2,%3};" \
                 : "+f"((c)[0]), "+f"((c)[1]), "+f"((c)[2]), "+f"((c)[3]) \
                 : "r"((a)[0]), "r"((a)[1]), "r"((a)[2]), "r"((a)[3]), \
                   "r"(b0v), "r"(b1v))

#define SWZ(x) ((uint32_t)(x) ^ ((((uint32_t)(x)) >> 3) & 0x70))

// fast e^x on the FMA pipe
__device__ __forceinline__ float fexp(float x) {
    float y = x * 1.44269504f;
    y = fmaxf(y, -100.f);
    float t = y + 12582912.0f;
    float nf = t - 12582912.0f;
    float f = y - nf;
    uint32_t sc = (__float_as_uint(t) << 23) + 0x3F800000u;
    float p = fmaf(f, 0.0096181291f, 0.0555041087f);
    p = fmaf(f, p, 0.2402265069f);
    p = fmaf(f, p, 0.6931471806f);
    p = fmaf(f, p, 1.0f);
    return p * __uint_as_float(sc);
}

__device__ __forceinline__ uint32_t packhf(float x, float y) {
    __half2 h = __floats2half2_rn(x, y);
    return *(uint32_t*)&h;
}

// ---------------------------------------------------------------------------
// fp32 -> bf16 hi/lo split for X inputs. blockIdx.y selects slot.
// ---------------------------------------------------------------------------
__global__ __launch_bounds__(256)
void conv_x_kernel(const float* __restrict__ Q, const float* __restrict__ K,
                   const float* __restrict__ V)
{
    const int slot = blockIdx.y;
    const float* X = (slot == 0) ? Q : (slot == 1) ? K : V;
    size_t i = (size_t)blockIdx.x * 256 + threadIdx.x;
    float4 v = ((const float4*)X)[i];
    __nv_bfloat16 h0 = __float2bfloat16(v.x), h1 = __float2bfloat16(v.y);
    __nv_bfloat16 h2 = __float2bfloat16(v.z), h3 = __float2bfloat16(v.w);
    __nv_bfloat16 l0 = __float2bfloat16(v.x - __bfloat162float(h0));
    __nv_bfloat16 l1 = __float2bfloat16(v.y - __bfloat162float(h1));
    __nv_bfloat16 l2 = __float2bfloat16(v.z - __bfloat162float(h2));
    __nv_bfloat16 l3 = __float2bfloat16(v.w - __bfloat162float(h3));
    __nv_bfloat162* hp = reinterpret_cast<__nv_bfloat162*>(g_xhi[slot] + i * 4);
    __nv_bfloat162* lp = reinterpret_cast<__nv_bfloat162*>(g_xlo[slot] + i * 4);
    __nv_bfloat162 a; a.x = h0; a.y = h1; hp[0] = a;
    __nv_bfloat162 b; b.x = h2; b.y = h3; hp[1] = b;
    __nv_bfloat162 c; c.x = l0; c.y = l1; lp[0] = c;
    __nv_bfloat162 d; d.x = l2; d.y = l3; lp[1] = d;
}

// ---------------------------------------------------------------------------
// W [K][N] fp32 -> transposed [N][K] bf16 hi/lo. blockIdx.z selects slot.
// ---------------------------------------------------------------------------
__global__ __launch_bounds__(256)
void conv_w_kernel(const float* __restrict__ WQ, const float* __restrict__ WK,
                   const float* __restrict__ WV)
{
    __shared__ float t[32][33];
    const int slot = blockIdx.z;
    const float* W = (slot == 0) ? WQ : (slot == 1) ? WK : WV;
    const int n0 = blockIdx.x * 32, k0 = blockIdx.y * 32;
    const int tx = threadIdx.x & 31, ty = threadIdx.x >> 5;
#pragma unroll
    for (int r = 0; r < 32; r += 8)
        t[ty + r][tx] = W[(size_t)(k0 + ty + r) * DM + n0 + tx];
    __syncthreads();
#pragma unroll
    for (int r = 0; r < 32; r += 8) {
        int n = ty + r;
        float x = t[tx][n];
        __nv_bfloat16 h = __float2bfloat16(x);
        float l = x - __bfloat162float(h);
        size_t o = (size_t)(n0 + n) * DIN + k0 + tx;
        g_whi[slot][o] = h;
        g_wlo[slot][o] = __float2bfloat16(l);
    }
}

// ---------------------------------------------------------------------------
// HMMA projection GEMM (bf16 3-term split), 2 CTAs/SM. fp16 [bh][s][hd] out.
// ---------------------------------------------------------------------------
#define PROJ_TILE_B   10240
#define PROJ_BUF_B    (4 * PROJ_TILE_B)
#define PROJ_SMEM     (2 * PROJ_BUF_B)

__global__ __launch_bounds__(256, 2)
void proj_mma_kernel(const float* __restrict__ bias, int which)
{
    extern __shared__ char dsm[];
    const uint32_t sbase = smem_u32(dsm);

    const __nv_bfloat16* Ah = g_xhi[which];
    const __nv_bfloat16* Al = g_xlo[which];
    const __nv_bfloat16* Bh = g_whi[which];
    const __nv_bfloat16* Bl = g_wlo[which];

    const int tid  = threadIdx.x;
    const int wid  = tid >> 5, lane = tid & 31;
    const int wm   = wid & 1;
    const int wn   = wid >> 1;
    const int row0 = blockIdx.y * 128, col0 = blockIdx.x * 128;

    const int lrow  = tid >> 1;
    const int lhalf = tid & 1;
    const uint32_t sdst = (uint32_t)(lrow * 80 + lhalf * 32);
    const char* gA_h = (const char*)(Ah + (size_t)(row0 + lrow) * DIN) + lhalf * 32;
    const char* gA_l = (const char*)(Al + (size_t)(row0 + lrow) * DIN) + lhalf * 32;
    const char* gB_h = (const char*)(Bh + (size_t)(col0 + lrow) * DIN) + lhalf * 32;
    const char* gB_l = (const char*)(Bl + (size_t)(col0 + lrow) * DIN) + lhalf * 32;

    const int r8 = lane & 7;
    const int ami = lane >> 3;
    const uint32_t a_off = (uint32_t)(((wm * 64 + (ami & 1) * 8 + r8) * 40
                                       + (ami >> 1) * 8) * 2);
    const int bmi = (lane >> 3) & 1;
    const uint32_t b_off = (uint32_t)(((wn * 32 + r8) * 40 + bmi * 8) * 2);

    float acc[4][4][4];
#pragma unroll
    for (int i = 0; i < 4; ++i)
#pragma unroll
        for (int j = 0; j < 4; ++j)
            acc[i][j][0] = acc[i][j][1] = acc[i][j][2] = acc[i][j][3] = 0.f;

    {
        uint32_t b0 = sbase;
        CP16(b0 + sdst,                    gA_h);
        CP16(b0 + sdst + 16,               gA_h + 16);
        CP16(b0 + PROJ_TILE_B + sdst,      gA_l);
        CP16(b0 + PROJ_TILE_B + sdst + 16, gA_l + 16);
        CP16(b0 + 2 * PROJ_TILE_B + sdst,      gB_h);
        CP16(b0 + 2 * PROJ_TILE_B + sdst + 16, gB_h + 16);
        CP16(b0 + 3 * PROJ_TILE_B + sdst,      gB_l);
        CP16(b0 + 3 * PROJ_TILE_B + sdst + 16, gB_l + 16);
        CP_COMMIT();
    }

    for (int c = 0; c < 32; ++c) {
        const uint32_t bufb = sbase + (uint32_t)(c & 1) * PROJ_BUF_B;
        if (c + 1 < 32) {
            const uint32_t nb = sbase + (uint32_t)((c + 1) & 1) * PROJ_BUF_B;
            const int kb = (c + 1) * 64;
            CP16(nb + sdst,                    gA_h + kb);
            CP16(nb + sdst + 16,               gA_h + kb + 16);
            CP16(nb + PROJ_TILE_B + sdst,      gA_l + kb);
            CP16(nb + PROJ_TILE_B + sdst + 16, gA_l + kb + 16);
            CP16(nb + 2 * PROJ_TILE_B + sdst,      gB_h + kb);
            CP16(nb + 2 * PROJ_TILE_B + sdst + 16, gB_h + kb + 16);
            CP16(nb + 3 * PROJ_TILE_B + sdst,      gB_l + kb);
            CP16(nb + 3 * PROJ_TILE_B + sdst + 16, gB_l + kb + 16);
            CP_COMMIT();
            CP_WAIT1();
        } else {
            CP_WAIT0();
        }
        __syncthreads();

#pragma unroll
        for (int ks = 0; ks < 32; ks += 16) {
            const uint32_t ab = bufb + a_off + (uint32_t)(ks * 2);
            const uint32_t bb = bufb + 2 * PROJ_TILE_B + b_off + (uint32_t)(ks * 2);

            uint32_t ah[4][4], bhf[4][2], blf[4][2];
#pragma unroll
            for (int mt = 0; mt < 4; ++mt)
                LDSM_X4(ah[mt][0], ah[mt][1], ah[mt][2], ah[mt][3],
                        ab + (uint32_t)(mt * 1280));
#pragma unroll
            for (int nt = 0; nt < 4; ++nt)
                LDSM_X2(bhf[nt][0], bhf[nt][1], bb + (uint32_t)(nt * 640));
#pragma unroll
            for (int mt = 0; mt < 4; ++mt)
#pragma unroll
                for (int nt = 0; nt < 4; ++nt)
                    MMA_BF16(acc[mt][nt], ah[mt], bhf[nt]);
#pragma unroll
            for (int nt = 0; nt < 4; ++nt)
                LDSM_X2(blf[nt][0], blf[nt][1],
                        bb + (uint32_t)(PROJ_TILE_B + nt * 640));
#pragma unroll
            for (int mt = 0; mt < 4; ++mt)
#pragma unroll
                for (int nt = 0; nt < 4; ++nt)
                    MMA_BF16(acc[mt][nt], ah[mt], blf[nt]);
#pragma unroll
            for (int mt = 0; mt < 4; ++mt)
                LDSM_X4(ah[mt][0], ah[mt][1], ah[mt][2], ah[mt][3],
                        ab + (uint32_t)(PROJ_TILE_B + mt * 1280));
#pragma unroll
            for (int mt = 0; mt < 4; ++mt)
#pragma unroll
                for (int nt = 0; nt < 4; ++nt)
                    MMA_BF16(acc[mt][nt], ah[mt], bhf[nt]);
        }
        __syncthreads();
    }

    // Epilogue: bias + fp16 [bh][s][hd] (uniform coalesced path for q/k/v)
    const int g  = lane >> 2;
    const int t2 = (lane & 3) * 2;
    const float scale = (which == 0) ? 0.125f : 1.0f;
    __half* dst = (which == 0) ? g_qh : (which == 1) ? g_kh : g_vh;
#pragma unroll
    for (int mt = 0; mt < 4; ++mt) {
        const int r0 = row0 + wm * 64 + mt * 16 + g;
        const int r1 = r0 + 8;
        const int bat = r0 >> 11;
        const int s0 = r0 & 2047, s1 = r1 & 2047;
#pragma unroll
        for (int nt = 0; nt < 4; ++nt) {
            const int col = col0 + wn * 32 + nt * 8 + t2;
            const float2 bv2 = *(const float2*)(bias + col);
            const int h = col >> 6, hd = col & 63;
            const int bh = bat * H_ + h;
            float v00 = (acc[mt][nt][0] + bv2.x) * scale;
            float v01 = (acc[mt][nt][1] + bv2.y) * scale;
            float v10 = (acc[mt][nt][2] + bv2.x) * scale;
            float v11 = (acc[mt][nt][3] + bv2.y) * scale;
            size_t o0 = ((size_t)bh * S_ + s0) * HD_ + hd;
            size_t o1 = ((size_t)bh * S_ + s1) * HD_ + hd;
            *(uint32_t*)(dst + o0) = packhf(v00, v01);
            *(uint32_t*)(dst + o1) = packhf(v10, v11);
        }
    }
}

// ---------------------------------------------------------------------------
// fp16 HMMA flash attention. BR=64, BC=64, 4 warps, 4 CTAs/SM.
// QK: qh x Kh. PV: (Ph+Pl) x Vh with V [keys][hd] + ldmatrix.trans.
// smem: Q 8K @32768, double-buffered {Kh 8K, Vh 8K} @0/@16384 = 40KB
// ---------------------------------------------------------------------------
#define ATTN_SMEM (40960 + 1024)

__global__ __launch_bounds__(128, 4)
void attn_mma_kernel(float* __restrict__ out)
{
    extern __shared__ char asmem[];
    const uint32_t sb = (smem_u32(asmem) + 1023u) & ~1023u;

    const int tid  = threadIdx.x;
    const int lane = tid & 31, warp = tid >> 5;
    const int bh   = blockIdx.y;
    const int q0   = blockIdx.x * 64;

    const char* qh = (const char*)(g_qh + (size_t)bh * S_ * HD_);
    const char* kh = (const char*)(g_kh + (size_t)bh * S_ * HD_);
    const char* vh = (const char*)(g_vh + (size_t)bh * S_ * HD_);

    const int r8 = lane & 7;
    const int arow = ((lane >> 3) & 1) * 8 + r8;
    const int acol = lane >> 4;

    const int lrow  = tid >> 1;       // 0..63
    const int lhalf = tid & 1;

    // ---- stage Q tile [64][64] ----
#pragma unroll
    for (int i = 0; i < 4; ++i) {
        int ch = lhalf * 4 + i;
        uint32_t off = SWZ(lrow * 128 + ch * 16);
        CP16(sb + 32768 + off, qh + (size_t)(q0 + lrow) * 128 + ch * 16);
    }
    CP_COMMIT();
    // ---- chunk 0 into buf0 (K and V share layout now) ----
#pragma unroll
    for (int i = 0; i < 4; ++i) {
        int ch = lhalf * 4 + i;
        uint32_t off = SWZ(lrow * 128 + ch * 16);
        CP16(sb + off,        kh + (size_t)lrow * 128 + ch * 16);
        CP16(sb + 8192 + off, vh + (size_t)lrow * 128 + ch * 16);
    }
    CP_COMMIT();
    CP_WAIT0();
    __syncthreads();

    // ---- Q fragments into registers ----
    uint32_t qa_h[4][4];
#pragma unroll
    for (int ks = 0; ks < 4; ++ks) {
        int row = warp * 16 + arow;
        int ch  = ks * 2 + acol;
        uint32_t off = SWZ(row * 128 + ch * 16);
        LDSM_X4(qa_h[ks][0], qa_h[ks][1], qa_h[ks][2], qa_h[ks][3], sb + 32768 + off);
    }

    float m0 = -1e30f, m1 = -1e30f, l0 = 0.f, l1 = 0.f;
    float o[8][4];
#pragma unroll
    for (int nt = 0; nt < 8; ++nt)
        o[nt][0] = o[nt][1] = o[nt][2] = o[nt][3] = 0.f;

    for (int c = 0; c < 32; ++c) {
        if (c > 0) CP_WAIT0();
        __syncthreads();
        if (c + 1 < 32) {
            const uint32_t nb = sb + (uint32_t)((c + 1) & 1) * 16384;
            const int kb = (c + 1) * 64;
#pragma unroll
            for (int i = 0; i < 4; ++i) {
                int ch = lhalf * 4 + i;
                uint32_t off = SWZ(lrow * 128 + ch * 16);
                CP16(nb + off,        kh + (size_t)(kb + lrow) * 128 + ch * 16);
                CP16(nb + 8192 + off, vh + (size_t)(kb + lrow) * 128 + ch * 16);
            }
            CP_COMMIT();
        }
        const uint32_t buf = sb + (uint32_t)(c & 1) * 16384;

        // ---- S = qh @ Kh^T ----
        float cc[8][4];
#pragma unroll
        for (int nt = 0; nt < 8; ++nt)
            cc[nt][0] = cc[nt][1] = cc[nt][2] = cc[nt][3] = 0.f;

#pragma unroll
        for (int ks = 0; ks < 4; ++ks) {
#pragma unroll
            for (int np = 0; np < 4; ++np) {
                uint32_t off = SWZ((np * 16 + arow) * 128 + (ks * 2 + acol) * 16);
                uint32_t b0, b1, b2, b3;
                LDSM_X4(b0, b1, b2, b3, buf + off);
                MMA_F16S(cc[2 * np],     qa_h[ks], b0, b2);
                MMA_F16S(cc[2 * np + 1], qa_h[ks], b1, b3);
            }
        }

        // ---- online softmax ----
        float rmx0 = cc[0][0], rmx1 = cc[0][2];
#pragma unroll
        for (int nt = 0; nt < 8; ++nt) {
            rmx0 = fmaxf(rmx0, fmaxf(cc[nt][0], cc[nt][1]));
            rmx1 = fmaxf(rmx1, fmaxf(cc[nt][2], cc[nt][3]));
        }
        rmx0 = fmaxf(rmx0, __shfl_xor_sync(0xffffffffu, rmx0, 1));
        rmx0 = fmaxf(rmx0, __shfl_xor_sync(0xffffffffu, rmx0, 2));
        rmx1 = fmaxf(rmx1, __shfl_xor_sync(0xffffffffu, rmx1, 1));
        rmx1 = fmaxf(rmx1, __shfl_xor_sync(0xffffffffu, rmx1, 2));
        float mn0 = fmaxf(m0, rmx0), mn1 = fmaxf(m1, rmx1);
        float cr0 = fexp(m0 - mn0), cr1 = fexp(m1 - mn1);
        m0 = mn0; m1 = mn1;
        float rs0 = 0.f, rs1 = 0.f;
#pragma unroll
        for (int nt = 0; nt < 8; ++nt) {
            cc[nt][0] = fexp(cc[nt][0] - mn0);
            cc[nt][1] = fexp(cc[nt][1] - mn0);
            cc[nt][2] = fexp(cc[nt][2] - mn1);
            cc[nt][3] = fexp(cc[nt][3] - mn1);
            rs0 += cc[nt][0] + cc[nt][1];
            rs1 += cc[nt][2] + cc[nt][3];
        }
        rs0 += __shfl_xor_sync(0xffffffffu, rs0, 1);
        rs0 += __shfl_xor_sync(0xffffffffu, rs0, 2);
        rs1 += __shfl_xor_sync(0xffffffffu, rs1, 1);
        rs1 += __shfl_xor_sync(0xffffffffu, rs1, 2);
        l0 = l0 * cr0 + rs0;
        l1 = l1 * cr1 + rs1;
#pragma unroll
        for (int nt = 0; nt < 8; ++nt) {
            o[nt][0] *= cr0; o[nt][1] *= cr0;
            o[nt][2] *= cr1; o[nt][3] *= cr1;
        }

        // ---- pack P into fp16 A fragments (hi/lo) ----
        uint32_t pa_h[4][4], pa_l[4][4];
#pragma unroll
        for (int j = 0; j < 4; ++j) {
            float x0 = cc[2 * j][0],     x1 = cc[2 * j][1];
            float x2 = cc[2 * j][2],     x3 = cc[2 * j][3];
            float x4 = cc[2 * j + 1][0], x5 = cc[2 * j + 1][1];
            float x6 = cc[2 * j + 1][2], x7 = cc[2 * j + 1][3];
            uint32_t h0 = packhf(x0, x1), h1 = packhf(x2, x3);
            uint32_t h2 = packhf(x4, x5), h3 = packhf(x6, x7);
            pa_h[j][0] = h0; pa_h[j][1] = h1; pa_h[j][2] = h2; pa_h[j][3] = h3;
            float2 f0 = __half22float2(*(__half2*)&h0);
            float2 f1 = __half22float2(*(__half2*)&h1);
            float2 f2 = __half22float2(*(__half2*)&h2);
            float2 f3 = __half22float2(*(__half2*)&h3);
            pa_l[j][0] = packhf(x0 - f0.x, x1 - f0.y);
            pa_l[j][1] = packhf(x2 - f1.x, x3 - f1.y);
            pa_l[j][2] = packhf(x4 - f2.x, x5 - f2.y);
            pa_l[j][3] = packhf(x6 - f3.x, x7 - f3.y);
        }

        // ---- O += (Ph + Pl) @ Vh  (V [keys][hd] via ldmatrix.trans) ----
#pragma unroll
        for (int j = 0; j < 4; ++j) {
#pragma unroll
            for (int np = 0; np < 4; ++np) {
                uint32_t off = SWZ((j * 16 + arow) * 128 + (np * 2 + acol) * 16);
                uint32_t b0, b1, b2, b3;
                LDSM_X4T(b0, b1, b2, b3, buf + 8192 + off);
                MMA_F16S(o[2 * np],     pa_h[j], b0, b1);
                MMA_F16S(o[2 * np + 1], pa_h[j], b2, b3);
                MMA_F16S(o[2 * np],     pa_l[j], b0, b1);
                MMA_F16S(o[2 * np + 1], pa_l[j], b2, b3);
            }
        }
    }

    // ---- epilogue ----
    const int g  = lane >> 2;
    const int t2 = (lane & 3) * 2;
    const int bat = bh >> 4, h = bh & 15;
    const int s0 = q0 + warp * 16 + g, s1 = s0 + 8;
    const float inv0 = 1.0f / l0, inv1 = 1.0f / l1;
#pragma unroll
    for (int nt = 0; nt < 8; ++nt) {
        int col = h * HD_ + nt * 8 + t2;
        float2 v0, v1;
        v0.x = o[nt][0] * inv0; v0.y = o[nt][1] * inv0;
        v1.x = o[nt][2] * inv1; v1.y = o[nt][3] * inv1;
        *(float2*)(out + ((size_t)bat * S_ + s0) * DM + col) = v0;
        *(float2*)(out + ((size_t)bat * S_ + s1) * DM + col) = v1;
    }
}

// ---------------------------------------------------------------------------
extern "C" void kernel_launch(void* const* d_in, const int* in_sizes, int n_in,
                              void* d_out, int out_size)
{
    (void)in_sizes; (void)n_in; (void)out_size;
    const float* Q  = (const float*)d_in[0];
    const float* V  = (const float*)d_in[1];
    const float* K  = (const float*)d_in[2];
    const float* wq = (const float*)d_in[3];
    const float* bq = (const float*)d_in[4];
    const float* wk = (const float*)d_in[5];
    const float* bk = (const float*)d_in[6];
    const float* wv = (const float*)d_in[7];
    const float* bv = (const float*)d_in[8];
    float* out = (float*)d_out;

    dim3 xg((MX * DIN) / 4 / 256, 3);
    conv_x_kernel<<<xg, 256>>>(Q, K, V);
    dim3 wg(DM / 32, DIN / 32, 3);
    conv_w_kernel<<<wg, 256>>>(wq, wk, wv);

    cudaFuncSetAttribute(proj_mma_kernel, cudaFuncAttributeMaxDynamicSharedMemorySize, PROJ_SMEM);
    dim3 pg(DM / 128, MX / 128);
    proj_mma_kernel<<<pg, 256, PROJ_SMEM>>>(bq, 0);
    proj_mma_kernel<<<pg, 256, PROJ_SMEM>>>(bk, 1);
    proj_mma_kernel<<<pg, 256, PROJ_SMEM>>>(bv, 2);

    cudaFuncSetAttribute(attn_mma_kernel, cudaFuncAttributeMaxDynamicSharedMemorySize, ATTN_SMEM);
    dim3 ag(S_ / 64, B_ * H_);
    attn_mma_kernel<<<ag, 128, ATTN_SMEM>>>(out);
}

// round 10
// speedup vs baseline: 2.6206x; 1.4337x over previous
#include <cuda_runtime.h>
#include <cuda_fp16.h>
#include <cstdint>

#define B_   4
#define S_   2048
#define DIN  1024
#define DM   1024
#define H_   16
#define HD_  64
#define MX   (B_ * S_)   // 8192

// ---------------- scratch (static device arrays: no allocs) ----------------
__device__ __half g_xh[3][(size_t)MX * DIN];    // X fp16 [M][K]
__device__ __half g_wh[3][(size_t)DM * DIN];    // W^T fp16 [N][K]
// projected tensors (fp16), all [bh][s][hd]: q pre-scaled by 0.125
__device__ __half g_qh[(size_t)64 * S_ * HD_];
__device__ __half g_kh[(size_t)64 * S_ * HD_];
__device__ __half g_vh[(size_t)64 * S_ * HD_];

// ---------------- PTX helpers (baseline sm_80-class ISA only) --------------
__device__ __forceinline__ uint32_t smem_u32(const void* p) {
    uint32_t a;
    asm("{ .reg .u64 t; cvta.to.shared.u64 t, %1; cvt.u32.u64 %0, t; }"
        : "=r"(a) : "l"(p));
    return a;
}

#define CP16(dst, src) \
    asm volatile("cp.async.cg.shared.global [%0], [%1], 16;" \
                 :: "r"(dst), "l"(src) : "memory")
#define CP_COMMIT() asm volatile("cp.async.commit_group;" ::: "memory")
#define CP_WAIT1()  asm volatile("cp.async.wait_group 1;" ::: "memory")
#define CP_WAIT0()  asm volatile("cp.async.wait_group 0;" ::: "memory")

#define LDSM_X4(r0, r1, r2, r3, a) \
    asm volatile("ldmatrix.sync.aligned.m8n8.x4.shared.b16 {%0,%1,%2,%3}, [%4];" \
                 : "=r"(r0), "=r"(r1), "=r"(r2), "=r"(r3) : "r"(a))
#define LDSM_X4T(r0, r1, r2, r3, a) \
    asm volatile("ldmatrix.sync.aligned.m8n8.x4.trans.shared.b16 {%0,%1,%2,%3}, [%4];" \
                 : "=r"(r0), "=r"(r1), "=r"(r2), "=r"(r3) : "r"(a))
#define LDSM_X2(r0, r1, a) \
    asm volatile("ldmatrix.sync.aligned.m8n8.x2.shared.b16 {%0,%1}, [%2];" \
                 : "=r"(r0), "=r"(r1) : "r"(a))

#define MMA_F16(c, a, b) \
    asm volatile("mma.sync.aligned.m16n8k16.row.col.f32.f16.f16.f32 " \
                 "{%0,%1,%2,%3}, {%4,%5,%6,%7}, {%8,%9}, {%0,%1,%2,%3};" \
                 : "+f"((c)[0]), "+f"((c)[1]), "+f"((c)[2]), "+f"((c)[3]) \
                 : "r"((a)[0]), "r"((a)[1]), "r"((a)[2]), "r"((a)[3]), \
                   "r"((b)[0]), "r"((b)[1]))
#define MMA_F16S(c, a, b0v, b1v) \
    asm volatile("mma.sync.aligned.m16n8k16.row.col.f32.f16.f16.f32 " \
                 "{%0,%1,%2,%3}, {%4,%5,%6,%7}, {%8,%9}, {%0,%1,%2,%3};" \
                 : "+f"((c)[0]), "+f"((c)[1]), "+f"((c)[2]), "+f"((c)[3]) \
                 : "r"((a)[0]), "r"((a)[1]), "r"((a)[2]), "r"((a)[3]), \
                   "r"(b0v), "r"(b1v))

#define SWZ(x) ((uint32_t)(x) ^ ((((uint32_t)(x)) >> 3) & 0x70))

// fast e^x on the FMA pipe
__device__ __forceinline__ float fexp(float x) {
    float y = x * 1.44269504f;
    y = fmaxf(y, -100.f);
    float t = y + 12582912.0f;
    float nf = t - 12582912.0f;
    float f = y - nf;
    uint32_t sc = (__float_as_uint(t) << 23) + 0x3F800000u;
    float p = fmaf(f, 0.0096181291f, 0.0555041087f);
    p = fmaf(f, p, 0.2402265069f);
    p = fmaf(f, p, 0.6931471806f);
    p = fmaf(f, p, 1.0f);
    return p * __uint_as_float(sc);
}

__device__ __forceinline__ uint32_t packhf(float x, float y) {
    __half2 h = __floats2half2_rn(x, y);
    return *(uint32_t*)&h;
}

// ---------------------------------------------------------------------------
// fp32 -> fp16 for X inputs. blockIdx.y selects slot.
// ---------------------------------------------------------------------------
__global__ __launch_bounds__(256)
void conv_x_kernel(const float* __restrict__ Q, const float* __restrict__ K,
                   const float* __restrict__ V)
{
    const int slot = blockIdx.y;
    const float* X = (slot == 0) ? Q : (slot == 1) ? K : V;
    size_t i = (size_t)blockIdx.x * 256 + threadIdx.x;
    float4 v = ((const float4*)X)[i];
    __half2* hp = reinterpret_cast<__half2*>(g_xh[slot] + i * 4);
    hp[0] = __floats2half2_rn(v.x, v.y);
    hp[1] = __floats2half2_rn(v.z, v.w);
}

// ---------------------------------------------------------------------------
// W [K][N] fp32 -> transposed [N][K] fp16. blockIdx.z selects slot.
// ---------------------------------------------------------------------------
__global__ __launch_bounds__(256)
void conv_w_kernel(const float* __restrict__ WQ, const float* __restrict__ WK,
                   const float* __restrict__ WV)
{
    __shared__ float t[32][33];
    const int slot = blockIdx.z;
    const float* W = (slot == 0) ? WQ : (slot == 1) ? WK : WV;
    const int n0 = blockIdx.x * 32, k0 = blockIdx.y * 32;
    const int tx = threadIdx.x & 31, ty = threadIdx.x >> 5;
#pragma unroll
    for (int r = 0; r < 32; r += 8)
        t[ty + r][tx] = W[(size_t)(k0 + ty + r) * DM + n0 + tx];
    __syncthreads();
#pragma unroll
    for (int r = 0; r < 32; r += 8) {
        int n = ty + r;
        g_wh[slot][(size_t)(n0 + n) * DIN + k0 + tx] = __float2half(t[tx][n]);
    }
}

// ---------------------------------------------------------------------------
// fp16 HMMA projection GEMM (single term). 128x128 CTA tile, K-chunk 32,
// double-buffered cp.async, 2 CTAs/SM. fp16 [bh][s][hd] out.
// Tile: 128 rows x 32 fp16 payload (64 B) padded to 80 B rows.
// ---------------------------------------------------------------------------
#define PROJ_TILE_B   10240              // 128 rows * 80 B
#define PROJ_BUF_B    (2 * PROJ_TILE_B)  // A, B tiles
#define PROJ_SMEM     (2 * PROJ_BUF_B)   // double buffer = 40960 B

__global__ __launch_bounds__(256, 2)
void proj_mma_kernel(const float* __restrict__ bias, int which)
{
    extern __shared__ char dsm[];
    const uint32_t sbase = smem_u32(dsm);

    const __half* Ah = g_xh[which];
    const __half* Bh = g_wh[which];

    const int tid  = threadIdx.x;
    const int wid  = tid >> 5, lane = tid & 31;
    const int wm   = wid & 1;
    const int wn   = wid >> 1;
    const int row0 = blockIdx.y * 128, col0 = blockIdx.x * 128;

    const int lrow  = tid >> 1;
    const int lhalf = tid & 1;
    const uint32_t sdst = (uint32_t)(lrow * 80 + lhalf * 32);
    const char* gA = (const char*)(Ah + (size_t)(row0 + lrow) * DIN) + lhalf * 32;
    const char* gB = (const char*)(Bh + (size_t)(col0 + lrow) * DIN) + lhalf * 32;

    const int r8 = lane & 7;
    const int ami = lane >> 3;
    const uint32_t a_off = (uint32_t)(((wm * 64 + (ami & 1) * 8 + r8) * 40
                                       + (ami >> 1) * 8) * 2);
    const int bmi = (lane >> 3) & 1;
    const uint32_t b_off = (uint32_t)(((wn * 32 + r8) * 40 + bmi * 8) * 2);

    float acc[4][4][4];
#pragma unroll
    for (int i = 0; i < 4; ++i)
#pragma unroll
        for (int j = 0; j < 4; ++j)
            acc[i][j][0] = acc[i][j][1] = acc[i][j][2] = acc[i][j][3] = 0.f;

    {
        uint32_t b0 = sbase;
        CP16(b0 + sdst,                    gA);
        CP16(b0 + sdst + 16,               gA + 16);
        CP16(b0 + PROJ_TILE_B + sdst,      gB);
        CP16(b0 + PROJ_TILE_B + sdst + 16, gB + 16);
        CP_COMMIT();
    }

    for (int c = 0; c < 32; ++c) {
        const uint32_t bufb = sbase + (uint32_t)(c & 1) * PROJ_BUF_B;
        if (c + 1 < 32) {
            const uint32_t nb = sbase + (uint32_t)((c + 1) & 1) * PROJ_BUF_B;
            const int kb = (c + 1) * 64;   // 64 BYTES = 32 fp16 per chunk (FIX)
            CP16(nb + sdst,                    gA + kb);
            CP16(nb + sdst + 16,               gA + kb + 16);
            CP16(nb + PROJ_TILE_B + sdst,      gB + kb);
            CP16(nb + PROJ_TILE_B + sdst + 16, gB + kb + 16);
            CP_COMMIT();
            CP_WAIT1();
        } else {
            CP_WAIT0();
        }
        __syncthreads();

#pragma unroll
        for (int ks = 0; ks < 32; ks += 16) {
            const uint32_t ab = bufb + a_off + (uint32_t)(ks * 2);
            const uint32_t bb = bufb + PROJ_TILE_B + b_off + (uint32_t)(ks * 2);

            uint32_t ah[4][4], bf[4][2];
#pragma unroll
            for (int mt = 0; mt < 4; ++mt)
                LDSM_X4(ah[mt][0], ah[mt][1], ah[mt][2], ah[mt][3],
                        ab + (uint32_t)(mt * 1280));
#pragma unroll
            for (int nt = 0; nt < 4; ++nt)
                LDSM_X2(bf[nt][0], bf[nt][1], bb + (uint32_t)(nt * 640));
#pragma unroll
            for (int mt = 0; mt < 4; ++mt)
#pragma unroll
                for (int nt = 0; nt < 4; ++nt)
                    MMA_F16(acc[mt][nt], ah[mt], bf[nt]);
        }
        __syncthreads();
    }

    // Epilogue: bias + fp16 [bh][s][hd]
    const int g  = lane >> 2;
    const int t2 = (lane & 3) * 2;
    const float scale = (which == 0) ? 0.125f : 1.0f;
    __half* dst = (which == 0) ? g_qh : (which == 1) ? g_kh : g_vh;
#pragma unroll
    for (int mt = 0; mt < 4; ++mt) {
        const int r0 = row0 + wm * 64 + mt * 16 + g;
        const int r1 = r0 + 8;
        const int bat = r0 >> 11;
        const int s0 = r0 & 2047, s1 = r1 & 2047;
#pragma unroll
        for (int nt = 0; nt < 4; ++nt) {
            const int col = col0 + wn * 32 + nt * 8 + t2;
            const float2 bv2 = *(const float2*)(bias + col);
            const int h = col >> 6, hd = col & 63;
            const int bh = bat * H_ + h;
            float v00 = (acc[mt][nt][0] + bv2.x) * scale;
            float v01 = (acc[mt][nt][1] + bv2.y) * scale;
            float v10 = (acc[mt][nt][2] + bv2.x) * scale;
            float v11 = (acc[mt][nt][3] + bv2.y) * scale;
            size_t o0 = ((size_t)bh * S_ + s0) * HD_ + hd;
            size_t o1 = ((size_t)bh * S_ + s1) * HD_ + hd;
            *(uint32_t*)(dst + o0) = packhf(v00, v01);
            *(uint32_t*)(dst + o1) = packhf(v10, v11);
        }
    }
}

// ---------------------------------------------------------------------------
// fp16 HMMA flash attention. BR=64, BC=64, 4 warps, 4 CTAs/SM.
// QK: qh x Kh. PV: (Ph+Pl) x Vh with V [keys][hd] + ldmatrix.trans.
// smem: Q 8K @32768, double-buffered {Kh 8K, Vh 8K} @0/@16384 = 40KB
// ---------------------------------------------------------------------------
#define ATTN_SMEM (40960 + 1024)

__global__ __launch_bounds__(128, 4)
void attn_mma_kernel(float* __restrict__ out)
{
    extern __shared__ char asmem[];
    const uint32_t sb = (smem_u32(asmem) + 1023u) & ~1023u;

    const int tid  = threadIdx.x;
    const int lane = tid & 31, warp = tid >> 5;
    const int bh   = blockIdx.y;
    const int q0   = blockIdx.x * 64;

    const char* qh = (const char*)(g_qh + (size_t)bh * S_ * HD_);
    const char* kh = (const char*)(g_kh + (size_t)bh * S_ * HD_);
    const char* vh = (const char*)(g_vh + (size_t)bh * S_ * HD_);

    const int r8 = lane & 7;
    const int arow = ((lane >> 3) & 1) * 8 + r8;
    const int acol = lane >> 4;

    const int lrow  = tid >> 1;       // 0..63
    const int lhalf = tid & 1;

    // ---- stage Q tile [64][64] ----
#pragma unroll
    for (int i = 0; i < 4; ++i) {
        int ch = lhalf * 4 + i;
        uint32_t off = SWZ(lrow * 128 + ch * 16);
        CP16(sb + 32768 + off, qh + (size_t)(q0 + lrow) * 128 + ch * 16);
    }
    CP_COMMIT();
    // ---- chunk 0 into buf0 ----
#pragma unroll
    for (int i = 0; i < 4; ++i) {
        int ch = lhalf * 4 + i;
        uint32_t off = SWZ(lrow * 128 + ch * 16);
        CP16(sb + off,        kh + (size_t)lrow * 128 + ch * 16);
        CP16(sb + 8192 + off, vh + (size_t)lrow * 128 + ch * 16);
    }
    CP_COMMIT();
    CP_WAIT0();
    __syncthreads();

    // ---- Q fragments into registers ----
    uint32_t qa_h[4][4];
#pragma unroll
    for (int ks = 0; ks < 4; ++ks) {
        int row = warp * 16 + arow;
        int ch  = ks * 2 + acol;
        uint32_t off = SWZ(row * 128 + ch * 16);
        LDSM_X4(qa_h[ks][0], qa_h[ks][1], qa_h[ks][2], qa_h[ks][3], sb + 32768 + off);
    }

    float m0 = -1e30f, m1 = -1e30f, l0 = 0.f, l1 = 0.f;
    float o[8][4];
#pragma unroll
    for (int nt = 0; nt < 8; ++nt)
        o[nt][0] = o[nt][1] = o[nt][2] = o[nt][3] = 0.f;

    for (int c = 0; c < 32; ++c) {
        if (c > 0) CP_WAIT0();
        __syncthreads();
        if (c + 1 < 32) {
            const uint32_t nb = sb + (uint32_t)((c + 1) & 1) * 16384;
            const int kb = (c + 1) * 64;
#pragma unroll
            for (int i = 0; i < 4; ++i) {
                int ch = lhalf * 4 + i;
                uint32_t off = SWZ(lrow * 128 + ch * 16);
                CP16(nb + off,        kh + (size_t)(kb + lrow) * 128 + ch * 16);
                CP16(nb + 8192 + off, vh + (size_t)(kb + lrow) * 128 + ch * 16);
            }
            CP_COMMIT();
        }
        const uint32_t buf = sb + (uint32_t)(c & 1) * 16384;

        // ---- S = qh @ Kh^T ----
        float cc[8][4];
#pragma unroll
        for (int nt = 0; nt < 8; ++nt)
            cc[nt][0] = cc[nt][1] = cc[nt][2] = cc[nt][3] = 0.f;

#pragma unroll
        for (int ks = 0; ks < 4; ++ks) {
#pragma unroll
            for (int np = 0; np < 4; ++np) {
                uint32_t off = SWZ((np * 16 + arow) * 128 + (ks * 2 + acol) * 16);
                uint32_t b0, b1, b2, b3;
                LDSM_X4(b0, b1, b2, b3, buf + off);
                MMA_F16S(cc[2 * np],     qa_h[ks], b0, b2);
                MMA_F16S(cc[2 * np + 1], qa_h[ks], b1, b3);
            }
        }

        // ---- online softmax ----
        float rmx0 = cc[0][0], rmx1 = cc[0][2];
#pragma unroll
        for (int nt = 0; nt < 8; ++nt) {
            rmx0 = fmaxf(rmx0, fmaxf(cc[nt][0], cc[nt][1]));
            rmx1 = fmaxf(rmx1, fmaxf(cc[nt][2], cc[nt][3]));
        }
        rmx0 = fmaxf(rmx0, __shfl_xor_sync(0xffffffffu, rmx0, 1));
        rmx0 = fmaxf(rmx0, __shfl_xor_sync(0xffffffffu, rmx0, 2));
        rmx1 = fmaxf(rmx1, __shfl_xor_sync(0xffffffffu, rmx1, 1));
        rmx1 = fmaxf(rmx1, __shfl_xor_sync(0xffffffffu, rmx1, 2));
        float mn0 = fmaxf(m0, rmx0), mn1 = fmaxf(m1, rmx1);
        float cr0 = fexp(m0 - mn0), cr1 = fexp(m1 - mn1);
        m0 = mn0; m1 = mn1;
        float rs0 = 0.f, rs1 = 0.f;
#pragma unroll
        for (int nt = 0; nt < 8; ++nt) {
            cc[nt][0] = fexp(cc[nt][0] - mn0);
            cc[nt][1] = fexp(cc[nt][1] - mn0);
            cc[nt][2] = fexp(cc[nt][2] - mn1);
            cc[nt][3] = fexp(cc[nt][3] - mn1);
            rs0 += cc[nt][0] + cc[nt][1];
            rs1 += cc[nt][2] + cc[nt][3];
        }
        rs0 += __shfl_xor_sync(0xffffffffu, rs0, 1);
        rs0 += __shfl_xor_sync(0xffffffffu, rs0, 2);
        rs1 += __shfl_xor_sync(0xffffffffu, rs1, 1);
        rs1 += __shfl_xor_sync(0xffffffffu, rs1, 2);
        l0 = l0 * cr0 + rs0;
        l1 = l1 * cr1 + rs1;
#pragma unroll
        for (int nt = 0; nt < 8; ++nt) {
            o[nt][0] *= cr0; o[nt][1] *= cr0;
            o[nt][2] *= cr1; o[nt][3] *= cr1;
        }

        // ---- pack P into fp16 A fragments (hi/lo) ----
        uint32_t pa_h[4][4], pa_l[4][4];
#pragma unroll
        for (int j = 0; j < 4; ++j) {
            float x0 = cc[2 * j][0],     x1 = cc[2 * j][1];
            float x2 = cc[2 * j][2],     x3 = cc[2 * j][3];
            float x4 = cc[2 * j + 1][0], x5 = cc[2 * j + 1][1];
            float x6 = cc[2 * j + 1][2], x7 = cc[2 * j + 1][3];
            uint32_t h0 = packhf(x0, x1), h1 = packhf(x2, x3);
            uint32_t h2 = packhf(x4, x5), h3 = packhf(x6, x7);
            pa_h[j][0] = h0; pa_h[j][1] = h1; pa_h[j][2] = h2; pa_h[j][3] = h3;
            float2 f0 = __half22float2(*(__half2*)&h0);
            float2 f1 = __half22float2(*(__half2*)&h1);
            float2 f2 = __half22float2(*(__half2*)&h2);
            float2 f3 = __half22float2(*(__half2*)&h3);
            pa_l[j][0] = packhf(x0 - f0.x, x1 - f0.y);
            pa_l[j][1] = packhf(x2 - f1.x, x3 - f1.y);
            pa_l[j][2] = packhf(x4 - f2.x, x5 - f2.y);
            pa_l[j][3] = packhf(x6 - f3.x, x7 - f3.y);
        }

        // ---- O += (Ph + Pl) @ Vh  (V [keys][hd] via ldmatrix.trans) ----
#pragma unroll
        for (int j = 0; j < 4; ++j) {
#pragma unroll
            for (int np = 0; np < 4; ++np) {
                uint32_t off = SWZ((j * 16 + arow) * 128 + (np * 2 + acol) * 16);
                uint32_t b0, b1, b2, b3;
                LDSM_X4T(b0, b1, b2, b3, buf + 8192 + off);
                MMA_F16S(o[2 * np],     pa_h[j], b0, b1);
                MMA_F16S(o[2 * np + 1], pa_h[j], b2, b3);
                MMA_F16S(o[2 * np],     pa_l[j], b0, b1);
                MMA_F16S(o[2 * np + 1], pa_l[j], b2, b3);
            }
        }
    }

    // ---- epilogue ----
    const int g  = lane >> 2;
    const int t2 = (lane & 3) * 2;
    const int bat = bh >> 4, h = bh & 15;
    const int s0 = q0 + warp * 16 + g, s1 = s0 + 8;
    const float inv0 = 1.0f / l0, inv1 = 1.0f / l1;
#pragma unroll
    for (int nt = 0; nt < 8; ++nt) {
        int col = h * HD_ + nt * 8 + t2;
        float2 v0, v1;
        v0.x = o[nt][0] * inv0; v0.y = o[nt][1] * inv0;
        v1.x = o[nt][2] * inv1; v1.y = o[nt][3] * inv1;
        *(float2*)(out + ((size_t)bat * S_ + s0) * DM + col) = v0;
        *(float2*)(out + ((size_t)bat * S_ + s1) * DM + col) = v1;
    }
}

// ---------------------------------------------------------------------------
extern "C" void kernel_launch(void* const* d_in, const int* in_sizes, int n_in,
                              void* d_out, int out_size)
{
    (void)in_sizes; (void)n_in; (void)out_size;
    const float* Q  = (const float*)d_in[0];
    const float* V  = (const float*)d_in[1];
    const float* K  = (const float*)d_in[2];
    const float* wq = (const float*)d_in[3];
    const float* bq = (const float*)d_in[4];
    const float* wk = (const float*)d_in[5];
    const float* bk = (const float*)d_in[6];
    const float* wv = (const float*)d_in[7];
    const float* bv = (const float*)d_in[8];
    float* out = (float*)d_out;

    dim3 xg((MX * DIN) / 4 / 256, 3);
    conv_x_kernel<<<xg, 256>>>(Q, K, V);
    dim3 wg(DM / 32, DIN / 32, 3);
    conv_w_kernel<<<wg, 256>>>(wq, wk, wv);

    cudaFuncSetAttribute(proj_mma_kernel, cudaFuncAttributeMaxDynamicSharedMemorySize, PROJ_SMEM);
    dim3 pg(DM / 128, MX / 128);
    proj_mma_kernel<<<pg, 256, PROJ_SMEM>>>(bq, 0);
    proj_mma_kernel<<<pg, 256, PROJ_SMEM>>>(bk, 1);
    proj_mma_kernel<<<pg, 256, PROJ_SMEM>>>(bv, 2);

    cudaFuncSetAttribute(attn_mma_kernel, cudaFuncAttributeMaxDynamicSharedMemorySize, ATTN_SMEM);
    dim3 ag(S_ / 64, B_ * H_);
    attn_mma_kernel<<<ag, 128, ATTN_SMEM>>>(out);
}

// round 11
// speedup vs baseline: 2.9394x; 1.1216x over previous
#include <cuda_runtime.h>
#include <cuda_fp16.h>
#include <cstdint>

#define B_   4
#define S_   2048
#define DIN  1024
#define DM   1024
#define H_   16
#define HD_  64
#define MX   (B_ * S_)   // 8192

// ---------------- scratch (static device arrays: no allocs) ----------------
__device__ __half g_xh[3][(size_t)MX * DIN];    // X fp16 [M][K]
__device__ __half g_wh[3][(size_t)DM * DIN];    // W^T fp16 [N][K]
// projected tensors (fp16), all [bh][s][hd]: q pre-scaled by 0.125
__device__ __half g_qh[(size_t)64 * S_ * HD_];
__device__ __half g_kh[(size_t)64 * S_ * HD_];
__device__ __half g_vh[(size_t)64 * S_ * HD_];

// ---------------- PTX helpers (baseline sm_80-class ISA only) --------------
__device__ __forceinline__ uint32_t smem_u32(const void* p) {
    uint32_t a;
    asm("{ .reg .u64 t; cvta.to.shared.u64 t, %1; cvt.u32.u64 %0, t; }"
        : "=r"(a) : "l"(p));
    return a;
}

#define CP16(dst, src) \
    asm volatile("cp.async.cg.shared.global [%0], [%1], 16;" \
                 :: "r"(dst), "l"(src) : "memory")
#define CP_COMMIT() asm volatile("cp.async.commit_group;" ::: "memory")
#define CP_WAIT1()  asm volatile("cp.async.wait_group 1;" ::: "memory")
#define CP_WAIT0()  asm volatile("cp.async.wait_group 0;" ::: "memory")

#define LDSM_X4(r0, r1, r2, r3, a) \
    asm volatile("ldmatrix.sync.aligned.m8n8.x4.shared.b16 {%0,%1,%2,%3}, [%4];" \
                 : "=r"(r0), "=r"(r1), "=r"(r2), "=r"(r3) : "r"(a))
#define LDSM_X4T(r0, r1, r2, r3, a) \
    asm volatile("ldmatrix.sync.aligned.m8n8.x4.trans.shared.b16 {%0,%1,%2,%3}, [%4];" \
                 : "=r"(r0), "=r"(r1), "=r"(r2), "=r"(r3) : "r"(a))

#define MMA_F16S(c, a, b0v, b1v) \
    asm volatile("mma.sync.aligned.m16n8k16.row.col.f32.f16.f16.f32 " \
                 "{%0,%1,%2,%3}, {%4,%5,%6,%7}, {%8,%9}, {%0,%1,%2,%3};" \
                 : "+f"((c)[0]), "+f"((c)[1]), "+f"((c)[2]), "+f"((c)[3]) \
                 : "r"((a)[0]), "r"((a)[1]), "r"((a)[2]), "r"((a)[3]), \
                   "r"(b0v), "r"(b1v))

#define SWZ(x) ((uint32_t)(x) ^ ((((uint32_t)(x)) >> 3) & 0x70))

// fast e^x on the FMA pipe
__device__ __forceinline__ float fexp(float x) {
    float y = x * 1.44269504f;
    y = fmaxf(y, -100.f);
    float t = y + 12582912.0f;
    float nf = t - 12582912.0f;
    float f = y - nf;
    uint32_t sc = (__float_as_uint(t) << 23) + 0x3F800000u;
    float p = fmaf(f, 0.0096181291f, 0.0555041087f);
    p = fmaf(f, p, 0.2402265069f);
    p = fmaf(f, p, 0.6931471806f);
    p = fmaf(f, p, 1.0f);
    return p * __uint_as_float(sc);
}

__device__ __forceinline__ uint32_t packhf(float x, float y) {
    __half2 h = __floats2half2_rn(x, y);
    return *(uint32_t*)&h;
}

// ---------------------------------------------------------------------------
// fp32 -> fp16 for X inputs. blockIdx.y selects slot.
// ---------------------------------------------------------------------------
__global__ __launch_bounds__(256)
void conv_x_kernel(const float* __restrict__ Q, const float* __restrict__ K,
                   const float* __restrict__ V)
{
    const int slot = blockIdx.y;
    const float* X = (slot == 0) ? Q : (slot == 1) ? K : V;
    size_t i = (size_t)blockIdx.x * 256 + threadIdx.x;
    float4 v = ((const float4*)X)[i];
    __half2* hp = reinterpret_cast<__half2*>(g_xh[slot] + i * 4);
    hp[0] = __floats2half2_rn(v.x, v.y);
    hp[1] = __floats2half2_rn(v.z, v.w);
}

// ---------------------------------------------------------------------------
// W [K][N] fp32 -> transposed [N][K] fp16. blockIdx.z selects slot.
// ---------------------------------------------------------------------------
__global__ __launch_bounds__(256)
void conv_w_kernel(const float* __restrict__ WQ, const float* __restrict__ WK,
                   const float* __restrict__ WV)
{
    __shared__ float t[32][33];
    const int slot = blockIdx.z;
    const float* W = (slot == 0) ? WQ : (slot == 1) ? WK : WV;
    const int n0 = blockIdx.x * 32, k0 = blockIdx.y * 32;
    const int tx = threadIdx.x & 31, ty = threadIdx.x >> 5;
#pragma unroll
    for (int r = 0; r < 32; r += 8)
        t[ty + r][tx] = W[(size_t)(k0 + ty + r) * DM + n0 + tx];
    __syncthreads();
#pragma unroll
    for (int r = 0; r < 32; r += 8) {
        int n = ty + r;
        g_wh[slot][(size_t)(n0 + n) * DIN + k0 + tx] = __float2half(t[tx][n]);
    }
}

// ---------------------------------------------------------------------------
// fp16 HMMA projection GEMM. 128x128 CTA tile, K-chunk 64 (128B rows, SW128
// swizzle), double-buffered cp.async, 2 CTAs/SM. fp16 [bh][s][hd] out.
// ---------------------------------------------------------------------------
#define PROJ_TILE_B   16384              // 128 rows * 128 B
#define PROJ_BUF_B    (2 * PROJ_TILE_B)  // A, B tiles
#define PROJ_SMEM     (2 * PROJ_BUF_B)   // double buffer = 65536 B

__global__ __launch_bounds__(256, 2)
void proj_mma_kernel(const float* __restrict__ bias, int which)
{
    extern __shared__ char dsm[];
    const uint32_t sbase = smem_u32(dsm);

    const __half* Ah = g_xh[which];
    const __half* Bh = g_wh[which];

    const int tid  = threadIdx.x;
    const int wid  = tid >> 5, lane = tid & 31;
    const int wm   = wid & 1;          // 64-row half
    const int wn   = wid >> 1;         // 32-col quarter
    const int row0 = blockIdx.y * 128, col0 = blockIdx.x * 128;

    // loader: each thread covers one row-half (4 x 16B chunks)
    const int lrow  = tid >> 1;        // 0..127
    const int lhalf = tid & 1;         // 0/1
    const char* gA = (const char*)(Ah + (size_t)(row0 + lrow) * DIN);
    const char* gB = (const char*)(Bh + (size_t)(col0 + lrow) * DIN);

    // ldmatrix lane components (same scheme as attn kernel)
    const int r8 = lane & 7;
    const int arow = ((lane >> 3) & 1) * 8 + r8;
    const int acol = lane >> 4;        // 0/1

    float acc[4][4][4];
#pragma unroll
    for (int i = 0; i < 4; ++i)
#pragma unroll
        for (int j = 0; j < 4; ++j)
            acc[i][j][0] = acc[i][j][1] = acc[i][j][2] = acc[i][j][3] = 0.f;

    // prefetch chunk 0 into buffer 0
#pragma unroll
    for (int i = 0; i < 4; ++i) {
        int ch = lhalf * 4 + i;
        uint32_t off = SWZ(lrow * 128 + ch * 16);
        CP16(sbase + off,               gA + ch * 16);
        CP16(sbase + PROJ_TILE_B + off, gB + ch * 16);
    }
    CP_COMMIT();

    for (int c = 0; c < 16; ++c) {
        if (c + 1 < 16) {
            const uint32_t nb = sbase + (uint32_t)((c + 1) & 1) * PROJ_BUF_B;
            const int kb = (c + 1) * 128;   // 128 B = 64 fp16 per chunk
#pragma unroll
            for (int i = 0; i < 4; ++i) {
                int ch = lhalf * 4 + i;
                uint32_t off = SWZ(lrow * 128 + ch * 16);
                CP16(nb + off,               gA + kb + ch * 16);
                CP16(nb + PROJ_TILE_B + off, gB + kb + ch * 16);
            }
            CP_COMMIT();
            CP_WAIT1();
        } else {
            CP_WAIT0();
        }
        __syncthreads();
        const uint32_t buf = sbase + (uint32_t)(c & 1) * PROJ_BUF_B;

#pragma unroll
        for (int ks = 0; ks < 4; ++ks) {
            const int ch = ks * 2 + acol;
            uint32_t ah[4][4], bf[2][4];
#pragma unroll
            for (int mt = 0; mt < 4; ++mt) {
                uint32_t off = SWZ((wm * 64 + mt * 16 + arow) * 128 + ch * 16);
                LDSM_X4(ah[mt][0], ah[mt][1], ah[mt][2], ah[mt][3], buf + off);
            }
#pragma unroll
            for (int nh = 0; nh < 2; ++nh) {
                uint32_t off = SWZ((wn * 32 + nh * 16 + arow) * 128 + ch * 16);
                LDSM_X4(bf[nh][0], bf[nh][1], bf[nh][2], bf[nh][3],
                        buf + PROJ_TILE_B + off);
            }
#pragma unroll
            for (int mt = 0; mt < 4; ++mt)
#pragma unroll
                for (int nh = 0; nh < 2; ++nh) {
                    MMA_F16S(acc[mt][2 * nh],     ah[mt], bf[nh][0], bf[nh][2]);
                    MMA_F16S(acc[mt][2 * nh + 1], ah[mt], bf[nh][1], bf[nh][3]);
                }
        }
        __syncthreads();
    }

    // Epilogue: bias + fp16 [bh][s][hd]
    const int g  = lane >> 2;
    const int t2 = (lane & 3) * 2;
    const float scale = (which == 0) ? 0.125f : 1.0f;
    __half* dst = (which == 0) ? g_qh : (which == 1) ? g_kh : g_vh;
#pragma unroll
    for (int mt = 0; mt < 4; ++mt) {
        const int r0 = row0 + wm * 64 + mt * 16 + g;
        const int r1 = r0 + 8;
        const int bat = r0 >> 11;
        const int s0 = r0 & 2047, s1 = r1 & 2047;
#pragma unroll
        for (int nt = 0; nt < 4; ++nt) {
            const int col = col0 + wn * 32 + nt * 8 + t2;
            const float2 bv2 = *(const float2*)(bias + col);
            const int h = col >> 6, hd = col & 63;
            const int bh = bat * H_ + h;
            float v00 = (acc[mt][nt][0] + bv2.x) * scale;
            float v01 = (acc[mt][nt][1] + bv2.y) * scale;
            float v10 = (acc[mt][nt][2] + bv2.x) * scale;
            float v11 = (acc[mt][nt][3] + bv2.y) * scale;
            size_t o0 = ((size_t)bh * S_ + s0) * HD_ + hd;
            size_t o1 = ((size_t)bh * S_ + s1) * HD_ + hd;
            *(uint32_t*)(dst + o0) = packhf(v00, v01);
            *(uint32_t*)(dst + o1) = packhf(v10, v11);
        }
    }
}

// ---------------------------------------------------------------------------
// fp16 HMMA flash attention. BR=64, BC=64, 4 warps, 4 CTAs/SM.
// QK: qh x Kh. PV: Ph x Vh (single term), V [keys][hd] via ldmatrix.trans.
// smem: Q 8K @32768, double-buffered {Kh 8K, Vh 8K} @0/@16384 = 40KB
// ---------------------------------------------------------------------------
#define ATTN_SMEM (40960 + 1024)

__global__ __launch_bounds__(128, 4)
void attn_mma_kernel(float* __restrict__ out)
{
    extern __shared__ char asmem[];
    const uint32_t sb = (smem_u32(asmem) + 1023u) & ~1023u;

    const int tid  = threadIdx.x;
    const int lane = tid & 31, warp = tid >> 5;
    const int bh   = blockIdx.y;
    const int q0   = blockIdx.x * 64;

    const char* qh = (const char*)(g_qh + (size_t)bh * S_ * HD_);
    const char* kh = (const char*)(g_kh + (size_t)bh * S_ * HD_);
    const char* vh = (const char*)(g_vh + (size_t)bh * S_ * HD_);

    const int r8 = lane & 7;
    const int arow = ((lane >> 3) & 1) * 8 + r8;
    const int acol = lane >> 4;

    const int lrow  = tid >> 1;       // 0..63
    const int lhalf = tid & 1;

    // ---- stage Q tile [64][64] ----
#pragma unroll
    for (int i = 0; i < 4; ++i) {
        int ch = lhalf * 4 + i;
        uint32_t off = SWZ(lrow * 128 + ch * 16);
        CP16(sb + 32768 + off, qh + (size_t)(q0 + lrow) * 128 + ch * 16);
    }
    CP_COMMIT();
    // ---- chunk 0 into buf0 ----
#pragma unroll
    for (int i = 0; i < 4; ++i) {
        int ch = lhalf * 4 + i;
        uint32_t off = SWZ(lrow * 128 + ch * 16);
        CP16(sb + off,        kh + (size_t)lrow * 128 + ch * 16);
        CP16(sb + 8192 + off, vh + (size_t)lrow * 128 + ch * 16);
    }
    CP_COMMIT();
    CP_WAIT0();
    __syncthreads();

    // ---- Q fragments into registers ----
    uint32_t qa_h[4][4];
#pragma unroll
    for (int ks = 0; ks < 4; ++ks) {
        int row = warp * 16 + arow;
        int ch  = ks * 2 + acol;
        uint32_t off = SWZ(row * 128 + ch * 16);
        LDSM_X4(qa_h[ks][0], qa_h[ks][1], qa_h[ks][2], qa_h[ks][3], sb + 32768 + off);
    }

    float m0 = -1e30f, m1 = -1e30f, l0 = 0.f, l1 = 0.f;
    float o[8][4];
#pragma unroll
    for (int nt = 0; nt < 8; ++nt)
        o[nt][0] = o[nt][1] = o[nt][2] = o[nt][3] = 0.f;

    for (int c = 0; c < 32; ++c) {
        if (c > 0) CP_WAIT0();
        __syncthreads();
        if (c + 1 < 32) {
            const uint32_t nb = sb + (uint32_t)((c + 1) & 1) * 16384;
            const int kb = (c + 1) * 64;
#pragma unroll
            for (int i = 0; i < 4; ++i) {
                int ch = lhalf * 4 + i;
                uint32_t off = SWZ(lrow * 128 + ch * 16);
                CP16(nb + off,        kh + (size_t)(kb + lrow) * 128 + ch * 16);
                CP16(nb + 8192 + off, vh + (size_t)(kb + lrow) * 128 + ch * 16);
            }
            CP_COMMIT();
        }
        const uint32_t buf = sb + (uint32_t)(c & 1) * 16384;

        // ---- S = qh @ Kh^T ----
        float cc[8][4];
#pragma unroll
        for (int nt = 0; nt < 8; ++nt)
            cc[nt][0] = cc[nt][1] = cc[nt][2] = cc[nt][3] = 0.f;

#pragma unroll
        for (int ks = 0; ks < 4; ++ks) {
#pragma unroll
            for (int np = 0; np < 4; ++np) {
                uint32_t off = SWZ((np * 16 + arow) * 128 + (ks * 2 + acol) * 16);
                uint32_t b0, b1, b2, b3;
                LDSM_X4(b0, b1, b2, b3, buf + off);
                MMA_F16S(cc[2 * np],     qa_h[ks], b0, b2);
                MMA_F16S(cc[2 * np + 1], qa_h[ks], b1, b3);
            }
        }

        // ---- online softmax ----
        float rmx0 = cc[0][0], rmx1 = cc[0][2];
#pragma unroll
        for (int nt = 0; nt < 8; ++nt) {
            rmx0 = fmaxf(rmx0, fmaxf(cc[nt][0], cc[nt][1]));
            rmx1 = fmaxf(rmx1, fmaxf(cc[nt][2], cc[nt][3]));
        }
        rmx0 = fmaxf(rmx0, __shfl_xor_sync(0xffffffffu, rmx0, 1));
        rmx0 = fmaxf(rmx0, __shfl_xor_sync(0xffffffffu, rmx0, 2));
        rmx1 = fmaxf(rmx1, __shfl_xor_sync(0xffffffffu, rmx1, 1));
        rmx1 = fmaxf(rmx1, __shfl_xor_sync(0xffffffffu, rmx1, 2));
        float mn0 = fmaxf(m0, rmx0), mn1 = fmaxf(m1, rmx1);
        float cr0 = fexp(m0 - mn0), cr1 = fexp(m1 - mn1);
        m0 = mn0; m1 = mn1;
        float rs0 = 0.f, rs1 = 0.f;
#pragma unroll
        for (int nt = 0; nt < 8; ++nt) {
            cc[nt][0] = fexp(cc[nt][0] - mn0);
            cc[nt][1] = fexp(cc[nt][1] - mn0);
            cc[nt][2] = fexp(cc[nt][2] - mn1);
            cc[nt][3] = fexp(cc[nt][3] - mn1);
            rs0 += cc[nt][0] + cc[nt][1];
            rs1 += cc[nt][2] + cc[nt][3];
        }
        rs0 += __shfl_xor_sync(0xffffffffu, rs0, 1);
        rs0 += __shfl_xor_sync(0xffffffffu, rs0, 2);
        rs1 += __shfl_xor_sync(0xffffffffu, rs1, 1);
        rs1 += __shfl_xor_sync(0xffffffffu, rs1, 2);
        l0 = l0 * cr0 + rs0;
        l1 = l1 * cr1 + rs1;
#pragma unroll
        for (int nt = 0; nt < 8; ++nt) {
            o[nt][0] *= cr0; o[nt][1] *= cr0;
            o[nt][2] *= cr1; o[nt][3] *= cr1;
        }

        // ---- pack P into fp16 A fragments (single term) ----
        uint32_t pa_h[4][4];
#pragma unroll
        for (int j = 0; j < 4; ++j) {
            pa_h[j][0] = packhf(cc[2 * j][0],     cc[2 * j][1]);
            pa_h[j][1] = packhf(cc[2 * j][2],     cc[2 * j][3]);
            pa_h[j][2] = packhf(cc[2 * j + 1][0], cc[2 * j + 1][1]);
            pa_h[j][3] = packhf(cc[2 * j + 1][2], cc[2 * j + 1][3]);
        }

        // ---- O += Ph @ Vh  (V [keys][hd] via ldmatrix.trans) ----
#pragma unroll
        for (int j = 0; j < 4; ++j) {
#pragma unroll
            for (int np = 0; np < 4; ++np) {
                uint32_t off = SWZ((j * 16 + arow) * 128 + (np * 2 + acol) * 16);
                uint32_t b0, b1, b2, b3;
                LDSM_X4T(b0, b1, b2, b3, buf + 8192 + off);
                MMA_F16S(o[2 * np],     pa_h[j], b0, b1);
                MMA_F16S(o[2 * np + 1], pa_h[j], b2, b3);
            }
        }
    }

    // ---- epilogue ----
    const int g  = lane >> 2;
    const int t2 = (lane & 3) * 2;
    const int bat = bh >> 4, h = bh & 15;
    const int s0 = q0 + warp * 16 + g, s1 = s0 + 8;
    const float inv0 = 1.0f / l0, inv1 = 1.0f / l1;
#pragma unroll
    for (int nt = 0; nt < 8; ++nt) {
        int col = h * HD_ + nt * 8 + t2;
        float2 v0, v1;
        v0.x = o[nt][0] * inv0; v0.y = o[nt][1] * inv0;
        v1.x = o[nt][2] * inv1; v1.y = o[nt][3] * inv1;
        *(float2*)(out + ((size_t)bat * S_ + s0) * DM + col) = v0;
        *(float2*)(out + ((size_t)bat * S_ + s1) * DM + col) = v1;
    }
}

// ---------------------------------------------------------------------------
extern "C" void kernel_launch(void* const* d_in, const int* in_sizes, int n_in,
                              void* d_out, int out_size)
{
    (void)in_sizes; (void)n_in; (void)out_size;
    const float* Q  = (const float*)d_in[0];
    const float* V  = (const float*)d_in[1];
    const float* K  = (const float*)d_in[2];
    const float* wq = (const float*)d_in[3];
    const float* bq = (const float*)d_in[4];
    const float* wk = (const float*)d_in[5];
    const float* bk = (const float*)d_in[6];
    const float* wv = (const float*)d_in[7];
    const float* bv = (const float*)d_in[8];
    float* out = (float*)d_out;

    dim3 xg((MX * DIN) / 4 / 256, 3);
    conv_x_kernel<<<xg, 256>>>(Q, K, V);
    dim3 wg(DM / 32, DIN / 32, 3);
    conv_w_kernel<<<wg, 256>>>(wq, wk, wv);

    cudaFuncSetAttribute(proj_mma_kernel, cudaFuncAttributeMaxDynamicSharedMemorySize, PROJ_SMEM);
    dim3 pg(DM / 128, MX / 128);
    proj_mma_kernel<<<pg, 256, PROJ_SMEM>>>(bq, 0);
    proj_mma_kernel<<<pg, 256, PROJ_SMEM>>>(bk, 1);
    proj_mma_kernel<<<pg, 256, PROJ_SMEM>>>(bv, 2);

    cudaFuncSetAttribute(attn_mma_kernel, cudaFuncAttributeMaxDynamicSharedMemorySize, ATTN_SMEM);
    dim3 ag(S_ / 64, B_ * H_);
    attn_mma_kernel<<<ag, 128, ATTN_SMEM>>>(out);
}

// round 12
// speedup vs baseline: 3.2753x; 1.1143x over previous
#include <cuda_runtime.h>
#include <cuda_fp16.h>
#include <cstdint>

#define B_   4
#define S_   2048
#define DIN  1024
#define DM   1024
#define H_   16
#define HD_  64
#define MX   (B_ * S_)   // 8192

// ---------------- scratch (static device arrays: no allocs) ----------------
__device__ __half g_xh[3][(size_t)MX * DIN];    // X fp16 [M][K]
__device__ __half g_wh[3][(size_t)DM * DIN];    // W^T fp16 [N][K]
// projected tensors (fp16), all [bh][s][hd]: q pre-scaled by 0.125*log2(e)
__device__ __half g_qh[(size_t)64 * S_ * HD_];
__device__ __half g_kh[(size_t)64 * S_ * HD_];
__device__ __half g_vh[(size_t)64 * S_ * HD_];

// ---------------- PTX helpers (baseline sm_80-class ISA only) --------------
__device__ __forceinline__ uint32_t smem_u32(const void* p) {
    uint32_t a;
    asm("{ .reg .u64 t; cvta.to.shared.u64 t, %1; cvt.u32.u64 %0, t; }"
        : "=r"(a) : "l"(p));
    return a;
}

#define CP16(dst, src) \
    asm volatile("cp.async.cg.shared.global [%0], [%1], 16;" \
                 :: "r"(dst), "l"(src) : "memory")
#define CP_COMMIT() asm volatile("cp.async.commit_group;" ::: "memory")
#define CP_WAIT1()  asm volatile("cp.async.wait_group 1;" ::: "memory")
#define CP_WAIT0()  asm volatile("cp.async.wait_group 0;" ::: "memory")

#define LDSM_X4(r0, r1, r2, r3, a) \
    asm volatile("ldmatrix.sync.aligned.m8n8.x4.shared.b16 {%0,%1,%2,%3}, [%4];" \
                 : "=r"(r0), "=r"(r1), "=r"(r2), "=r"(r3) : "r"(a))
#define LDSM_X4T(r0, r1, r2, r3, a) \
    asm volatile("ldmatrix.sync.aligned.m8n8.x4.trans.shared.b16 {%0,%1,%2,%3}, [%4];" \
                 : "=r"(r0), "=r"(r1), "=r"(r2), "=r"(r3) : "r"(a))

#define MMA_F16S(c, a, b0v, b1v) \
    asm volatile("mma.sync.aligned.m16n8k16.row.col.f32.f16.f16.f32 " \
                 "{%0,%1,%2,%3}, {%4,%5,%6,%7}, {%8,%9}, {%0,%1,%2,%3};" \
                 : "+f"((c)[0]), "+f"((c)[1]), "+f"((c)[2]), "+f"((c)[3]) \
                 : "r"((a)[0]), "r"((a)[1]), "r"((a)[2]), "r"((a)[3]), \
                   "r"(b0v), "r"(b1v))

#define SWZ(x) ((uint32_t)(x) ^ ((((uint32_t)(x)) >> 3) & 0x70))

// exp2 on the MUFU pipe (scores pre-scaled into log2 domain)
__device__ __forceinline__ float fex2(float x) {
    float r;
    x = fmaxf(x, -126.f);
    asm("ex2.approx.f32 %0, %1;" : "=f"(r) : "f"(x));
    return r;
}

__device__ __forceinline__ uint32_t packhf(float x, float y) {
    __half2 h = __floats2half2_rn(x, y);
    return *(uint32_t*)&h;
}

// ---------------------------------------------------------------------------
// fp32 -> fp16 for X inputs. blockIdx.y selects slot.
// ---------------------------------------------------------------------------
__global__ __launch_bounds__(256)
void conv_x_kernel(const float* __restrict__ Q, const float* __restrict__ K,
                   const float* __restrict__ V)
{
    const int slot = blockIdx.y;
    const float* X = (slot == 0) ? Q : (slot == 1) ? K : V;
    size_t i = (size_t)blockIdx.x * 256 + threadIdx.x;
    float4 v = ((const float4*)X)[i];
    __half2* hp = reinterpret_cast<__half2*>(g_xh[slot] + i * 4);
    hp[0] = __floats2half2_rn(v.x, v.y);
    hp[1] = __floats2half2_rn(v.z, v.w);
}

// ---------------------------------------------------------------------------
// W [K][N] fp32 -> transposed [N][K] fp16. blockIdx.z selects slot.
// ---------------------------------------------------------------------------
__global__ __launch_bounds__(256)
void conv_w_kernel(const float* __restrict__ WQ, const float* __restrict__ WK,
                   const float* __restrict__ WV)
{
    __shared__ float t[32][33];
    const int slot = blockIdx.z;
    const float* W = (slot == 0) ? WQ : (slot == 1) ? WK : WV;
    const int n0 = blockIdx.x * 32, k0 = blockIdx.y * 32;
    const int tx = threadIdx.x & 31, ty = threadIdx.x >> 5;
#pragma unroll
    for (int r = 0; r < 32; r += 8)
        t[ty + r][tx] = W[(size_t)(k0 + ty + r) * DM + n0 + tx];
    __syncthreads();
#pragma unroll
    for (int r = 0; r < 32; r += 8) {
        int n = ty + r;
        g_wh[slot][(size_t)(n0 + n) * DIN + k0 + tx] = __float2half(t[tx][n]);
    }
}

// ---------------------------------------------------------------------------
// fp16 HMMA projection GEMM. 128x128 CTA tile, K-chunk 64 (128B rows, SW128
// swizzle), double-buffered cp.async, 2 CTAs/SM. fp16 [bh][s][hd] out.
// ---------------------------------------------------------------------------
#define PROJ_TILE_B   16384              // 128 rows * 128 B
#define PROJ_BUF_B    (2 * PROJ_TILE_B)  // A, B tiles
#define PROJ_SMEM     (2 * PROJ_BUF_B)   // double buffer = 65536 B

__global__ __launch_bounds__(256, 2)
void proj_mma_kernel(const float* __restrict__ bias, int which)
{
    extern __shared__ char dsm[];
    const uint32_t sbase = smem_u32(dsm);

    const __half* Ah = g_xh[which];
    const __half* Bh = g_wh[which];

    const int tid  = threadIdx.x;
    const int wid  = tid >> 5, lane = tid & 31;
    const int wm   = wid & 1;
    const int wn   = wid >> 1;
    const int row0 = blockIdx.y * 128, col0 = blockIdx.x * 128;

    const int lrow  = tid >> 1;
    const int lhalf = tid & 1;
    const char* gA = (const char*)(Ah + (size_t)(row0 + lrow) * DIN);
    const char* gB = (const char*)(Bh + (size_t)(col0 + lrow) * DIN);

    const int r8 = lane & 7;
    const int arow = ((lane >> 3) & 1) * 8 + r8;
    const int acol = lane >> 4;

    float acc[4][4][4];
#pragma unroll
    for (int i = 0; i < 4; ++i)
#pragma unroll
        for (int j = 0; j < 4; ++j)
            acc[i][j][0] = acc[i][j][1] = acc[i][j][2] = acc[i][j][3] = 0.f;

#pragma unroll
    for (int i = 0; i < 4; ++i) {
        int ch = lhalf * 4 + i;
        uint32_t off = SWZ(lrow * 128 + ch * 16);
        CP16(sbase + off,               gA + ch * 16);
        CP16(sbase + PROJ_TILE_B + off, gB + ch * 16);
    }
    CP_COMMIT();

    for (int c = 0; c < 16; ++c) {
        if (c + 1 < 16) {
            const uint32_t nb = sbase + (uint32_t)((c + 1) & 1) * PROJ_BUF_B;
            const int kb = (c + 1) * 128;
#pragma unroll
            for (int i = 0; i < 4; ++i) {
                int ch = lhalf * 4 + i;
                uint32_t off = SWZ(lrow * 128 + ch * 16);
                CP16(nb + off,               gA + kb + ch * 16);
                CP16(nb + PROJ_TILE_B + off, gB + kb + ch * 16);
            }
            CP_COMMIT();
            CP_WAIT1();
        } else {
            CP_WAIT0();
        }
        __syncthreads();
        const uint32_t buf = sbase + (uint32_t)(c & 1) * PROJ_BUF_B;

#pragma unroll
        for (int ks = 0; ks < 4; ++ks) {
            const int ch = ks * 2 + acol;
            uint32_t ah[4][4], bf[2][4];
#pragma unroll
            for (int mt = 0; mt < 4; ++mt) {
                uint32_t off = SWZ((wm * 64 + mt * 16 + arow) * 128 + ch * 16);
                LDSM_X4(ah[mt][0], ah[mt][1], ah[mt][2], ah[mt][3], buf + off);
            }
#pragma unroll
            for (int nh = 0; nh < 2; ++nh) {
                uint32_t off = SWZ((wn * 32 + nh * 16 + arow) * 128 + ch * 16);
                LDSM_X4(bf[nh][0], bf[nh][1], bf[nh][2], bf[nh][3],
                        buf + PROJ_TILE_B + off);
            }
#pragma unroll
            for (int mt = 0; mt < 4; ++mt)
#pragma unroll
                for (int nh = 0; nh < 2; ++nh) {
                    MMA_F16S(acc[mt][2 * nh],     ah[mt], bf[nh][0], bf[nh][2]);
                    MMA_F16S(acc[mt][2 * nh + 1], ah[mt], bf[nh][1], bf[nh][3]);
                }
        }
        __syncthreads();
    }

    // Epilogue: bias + fp16 [bh][s][hd]. q scaled by 0.125*log2(e).
    const int g  = lane >> 2;
    const int t2 = (lane & 3) * 2;
    const float scale = (which == 0) ? 0.125f * 1.44269504f : 1.0f;
    __half* dst = (which == 0) ? g_qh : (which == 1) ? g_kh : g_vh;
#pragma unroll
    for (int mt = 0; mt < 4; ++mt) {
        const int r0 = row0 + wm * 64 + mt * 16 + g;
        const int r1 = r0 + 8;
        const int bat = r0 >> 11;
        const int s0 = r0 & 2047, s1 = r1 & 2047;
#pragma unroll
        for (int nt = 0; nt < 4; ++nt) {
            const int col = col0 + wn * 32 + nt * 8 + t2;
            const float2 bv2 = *(const float2*)(bias + col);
            const int h = col >> 6, hd = col & 63;
            const int bh = bat * H_ + h;
            float v00 = (acc[mt][nt][0] + bv2.x) * scale;
            float v01 = (acc[mt][nt][1] + bv2.y) * scale;
            float v10 = (acc[mt][nt][2] + bv2.x) * scale;
            float v11 = (acc[mt][nt][3] + bv2.y) * scale;
            size_t o0 = ((size_t)bh * S_ + s0) * HD_ + hd;
            size_t o1 = ((size_t)bh * S_ + s1) * HD_ + hd;
            *(uint32_t*)(dst + o0) = packhf(v00, v01);
            *(uint32_t*)(dst + o1) = packhf(v10, v11);
        }
    }
}

// ---------------------------------------------------------------------------
// fp16 HMMA flash attention (log2-domain scores, MUFU ex2 softmax).
// BR=64, BC=64, 4 warps, 4 CTAs/SM. QK: qh x Kh. PV: Ph x Vh (ldmatrix.trans).
// smem: Q 8K @32768, double-buffered {Kh 8K, Vh 8K} @0/@16384 = 40KB
// ---------------------------------------------------------------------------
#define ATTN_SMEM (40960 + 1024)

__global__ __launch_bounds__(128, 4)
void attn_mma_kernel(float* __restrict__ out)
{
    extern __shared__ char asmem[];
    const uint32_t sb = (smem_u32(asmem) + 1023u) & ~1023u;

    const int tid  = threadIdx.x;
    const int lane = tid & 31, warp = tid >> 5;
    const int bh   = blockIdx.y;
    const int q0   = blockIdx.x * 64;

    const char* qh = (const char*)(g_qh + (size_t)bh * S_ * HD_);
    const char* kh = (const char*)(g_kh + (size_t)bh * S_ * HD_);
    const char* vh = (const char*)(g_vh + (size_t)bh * S_ * HD_);

    const int r8 = lane & 7;
    const int arow = ((lane >> 3) & 1) * 8 + r8;
    const int acol = lane >> 4;

    const int lrow  = tid >> 1;       // 0..63
    const int lhalf = tid & 1;

    // ---- stage Q tile [64][64] ----
#pragma unroll
    for (int i = 0; i < 4; ++i) {
        int ch = lhalf * 4 + i;
        uint32_t off = SWZ(lrow * 128 + ch * 16);
        CP16(sb + 32768 + off, qh + (size_t)(q0 + lrow) * 128 + ch * 16);
    }
    CP_COMMIT();
    // ---- chunk 0 into buf0 ----
#pragma unroll
    for (int i = 0; i < 4; ++i) {
        int ch = lhalf * 4 + i;
        uint32_t off = SWZ(lrow * 128 + ch * 16);
        CP16(sb + off,        kh + (size_t)lrow * 128 + ch * 16);
        CP16(sb + 8192 + off, vh + (size_t)lrow * 128 + ch * 16);
    }
    CP_COMMIT();
    CP_WAIT0();
    __syncthreads();

    // ---- Q fragments into registers ----
    uint32_t qa_h[4][4];
#pragma unroll
    for (int ks = 0; ks < 4; ++ks) {
        int row = warp * 16 + arow;
        int ch  = ks * 2 + acol;
        uint32_t off = SWZ(row * 128 + ch * 16);
        LDSM_X4(qa_h[ks][0], qa_h[ks][1], qa_h[ks][2], qa_h[ks][3], sb + 32768 + off);
    }

    float m0 = -1e30f, m1 = -1e30f, l0 = 0.f, l1 = 0.f;
    float o[8][4];
#pragma unroll
    for (int nt = 0; nt < 8; ++nt)
        o[nt][0] = o[nt][1] = o[nt][2] = o[nt][3] = 0.f;

    for (int c = 0; c < 32; ++c) {
        if (c > 0) CP_WAIT0();
        __syncthreads();
        if (c + 1 < 32) {
            const uint32_t nb = sb + (uint32_t)((c + 1) & 1) * 16384;
            const int kb = (c + 1) * 64;
#pragma unroll
            for (int i = 0; i < 4; ++i) {
                int ch = lhalf * 4 + i;
                uint32_t off = SWZ(lrow * 128 + ch * 16);
                CP16(nb + off,        kh + (size_t)(kb + lrow) * 128 + ch * 16);
                CP16(nb + 8192 + off, vh + (size_t)(kb + lrow) * 128 + ch * 16);
            }
            CP_COMMIT();
        }
        const uint32_t buf = sb + (uint32_t)(c & 1) * 16384;

        // ---- S = qh @ Kh^T  (log2-domain scores) ----
        float cc[8][4];
#pragma unroll
        for (int nt = 0; nt < 8; ++nt)
            cc[nt][0] = cc[nt][1] = cc[nt][2] = cc[nt][3] = 0.f;

#pragma unroll
        for (int ks = 0; ks < 4; ++ks) {
#pragma unroll
            for (int np = 0; np < 4; ++np) {
                uint32_t off = SWZ((np * 16 + arow) * 128 + (ks * 2 + acol) * 16);
                uint32_t b0, b1, b2, b3;
                LDSM_X4(b0, b1, b2, b3, buf + off);
                MMA_F16S(cc[2 * np],     qa_h[ks], b0, b2);
                MMA_F16S(cc[2 * np + 1], qa_h[ks], b1, b3);
            }
        }

        // ---- online softmax (exp2 on MUFU pipe) ----
        float rmx0 = cc[0][0], rmx1 = cc[0][2];
#pragma unroll
        for (int nt = 0; nt < 8; ++nt) {
            rmx0 = fmaxf(rmx0, fmaxf(cc[nt][0], cc[nt][1]));
            rmx1 = fmaxf(rmx1, fmaxf(cc[nt][2], cc[nt][3]));
        }
        rmx0 = fmaxf(rmx0, __shfl_xor_sync(0xffffffffu, rmx0, 1));
        rmx0 = fmaxf(rmx0, __shfl_xor_sync(0xffffffffu, rmx0, 2));
        rmx1 = fmaxf(rmx1, __shfl_xor_sync(0xffffffffu, rmx1, 1));
        rmx1 = fmaxf(rmx1, __shfl_xor_sync(0xffffffffu, rmx1, 2));
        float mn0 = fmaxf(m0, rmx0), mn1 = fmaxf(m1, rmx1);
        float cr0 = fex2(m0 - mn0), cr1 = fex2(m1 - mn1);
        m0 = mn0; m1 = mn1;
        float rs0 = 0.f, rs1 = 0.f;
#pragma unroll
        for (int nt = 0; nt < 8; ++nt) {
            cc[nt][0] = fex2(cc[nt][0] - mn0);
            cc[nt][1] = fex2(cc[nt][1] - mn0);
            cc[nt][2] = fex2(cc[nt][2] - mn1);
            cc[nt][3] = fex2(cc[nt][3] - mn1);
            rs0 += cc[nt][0] + cc[nt][1];
            rs1 += cc[nt][2] + cc[nt][3];
        }
        rs0 += __shfl_xor_sync(0xffffffffu, rs0, 1);
        rs0 += __shfl_xor_sync(0xffffffffu, rs0, 2);
        rs1 += __shfl_xor_sync(0xffffffffu, rs1, 1);
        rs1 += __shfl_xor_sync(0xffffffffu, rs1, 2);
        l0 = l0 * cr0 + rs0;
        l1 = l1 * cr1 + rs1;
#pragma unroll
        for (int nt = 0; nt < 8; ++nt) {
            o[nt][0] *= cr0; o[nt][1] *= cr0;
            o[nt][2] *= cr1; o[nt][3] *= cr1;
        }

        // ---- pack P into fp16 A fragments ----
        uint32_t pa_h[4][4];
#pragma unroll
        for (int j = 0; j < 4; ++j) {
            pa_h[j][0] = packhf(cc[2 * j][0],     cc[2 * j][1]);
            pa_h[j][1] = packhf(cc[2 * j][2],     cc[2 * j][3]);
            pa_h[j][2] = packhf(cc[2 * j + 1][0], cc[2 * j + 1][1]);
            pa_h[j][3] = packhf(cc[2 * j + 1][2], cc[2 * j + 1][3]);
        }

        // ---- O += Ph @ Vh ----
#pragma unroll
        for (int j = 0; j < 4; ++j) {
#pragma unroll
            for (int np = 0; np < 4; ++np) {
                uint32_t off = SWZ((j * 16 + arow) * 128 + (np * 2 + acol) * 16);
                uint32_t b0, b1, b2, b3;
                LDSM_X4T(b0, b1, b2, b3, buf + 8192 + off);
                MMA_F16S(o[2 * np],     pa_h[j], b0, b1);
                MMA_F16S(o[2 * np + 1], pa_h[j], b2, b3);
            }
        }
    }

    // ---- epilogue ----
    const int g  = lane >> 2;
    const int t2 = (lane & 3) * 2;
    const int bat = bh >> 4, h = bh & 15;
    const int s0 = q0 + warp * 16 + g, s1 = s0 + 8;
    const float inv0 = 1.0f / l0, inv1 = 1.0f / l1;
#pragma unroll
    for (int nt = 0; nt < 8; ++nt) {
        int col = h * HD_ + nt * 8 + t2;
        float2 v0, v1;
        v0.x = o[nt][0] * inv0; v0.y = o[nt][1] * inv0;
        v1.x = o[nt][2] * inv1; v1.y = o[nt][3] * inv1;
        *(float2*)(out + ((size_t)bat * S_ + s0) * DM + col) = v0;
        *(float2*)(out + ((size_t)bat * S_ + s1) * DM + col) = v1;
    }
}

// ---------------------------------------------------------------------------
extern "C" void kernel_launch(void* const* d_in, const int* in_sizes, int n_in,
                              void* d_out, int out_size)
{
    (void)in_sizes; (void)n_in; (void)out_size;
    const float* Q  = (const float*)d_in[0];
    const float* V  = (const float*)d_in[1];
    const float* K  = (const float*)d_in[2];
    const float* wq = (const float*)d_in[3];
    const float* bq = (const float*)d_in[4];
    const float* wk = (const float*)d_in[5];
    const float* bk = (const float*)d_in[6];
    const float* wv = (const float*)d_in[7];
    const float* bv = (const float*)d_in[8];
    float* out = (float*)d_out;

    dim3 xg((MX * DIN) / 4 / 256, 3);
    conv_x_kernel<<<xg, 256>>>(Q, K, V);
    dim3 wg(DM / 32, DIN / 32, 3);
    conv_w_kernel<<<wg, 256>>>(wq, wk, wv);

    cudaFuncSetAttribute(proj_mma_kernel, cudaFuncAttributeMaxDynamicSharedMemorySize, PROJ_SMEM);
    dim3 pg(DM / 128, MX / 128);
    proj_mma_kernel<<<pg, 256, PROJ_SMEM>>>(bq, 0);
    proj_mma_kernel<<<pg, 256, PROJ_SMEM>>>(bk, 1);
    proj_mma_kernel<<<pg, 256, PROJ_SMEM>>>(bv, 2);

    cudaFuncSetAttribute(attn_mma_kernel, cudaFuncAttributeMaxDynamicSharedMemorySize, ATTN_SMEM);
    dim3 ag(S_ / 64, B_ * H_);
    attn_mma_kernel<<<ag, 128, ATTN_SMEM>>>(out);
}

// round 13
// speedup vs baseline: 3.2888x; 1.0041x over previous
#include <cuda_runtime.h>
#include <cuda_fp16.h>
#include <cstdint>

#define B_   4
#define S_   2048
#define DIN  1024
#define DM   1024
#define H_   16
#define HD_  64
#define MX   (B_ * S_)   // 8192

// ---------------- scratch (static device arrays: no allocs) ----------------
__device__ __half g_xh[3][(size_t)MX * DIN];    // X fp16 [M][K]
__device__ __half g_wh[3][(size_t)DM * DIN];    // W^T fp16 [N][K]
// projected tensors (fp16), all [bh][s][hd]: q pre-scaled by 0.125*log2(e)
__device__ __half g_qh[(size_t)64 * S_ * HD_];
__device__ __half g_kh[(size_t)64 * S_ * HD_];
__device__ __half g_vh[(size_t)64 * S_ * HD_];

// ---------------- PTX helpers (baseline sm_80-class ISA only) --------------
__device__ __forceinline__ uint32_t smem_u32(const void* p) {
    uint32_t a;
    asm("{ .reg .u64 t; cvta.to.shared.u64 t, %1; cvt.u32.u64 %0, t; }"
        : "=r"(a) : "l"(p));
    return a;
}

#define CP16(dst, src) \
    asm volatile("cp.async.cg.shared.global [%0], [%1], 16;" \
                 :: "r"(dst), "l"(src) : "memory")
#define CP_COMMIT() asm volatile("cp.async.commit_group;" ::: "memory")
#define CP_WAIT1()  asm volatile("cp.async.wait_group 1;" ::: "memory")
#define CP_WAIT0()  asm volatile("cp.async.wait_group 0;" ::: "memory")

#define LDSM_X4(r0, r1, r2, r3, a) \
    asm volatile("ldmatrix.sync.aligned.m8n8.x4.shared.b16 {%0,%1,%2,%3}, [%4];" \
                 : "=r"(r0), "=r"(r1), "=r"(r2), "=r"(r3) : "r"(a))
#define LDSM_X4T(r0, r1, r2, r3, a) \
    asm volatile("ldmatrix.sync.aligned.m8n8.x4.trans.shared.b16 {%0,%1,%2,%3}, [%4];" \
                 : "=r"(r0), "=r"(r1), "=r"(r2), "=r"(r3) : "r"(a))

#define MMA_F16S(c, a, b0v, b1v) \
    asm volatile("mma.sync.aligned.m16n8k16.row.col.f32.f16.f16.f32 " \
                 "{%0,%1,%2,%3}, {%4,%5,%6,%7}, {%8,%9}, {%0,%1,%2,%3};" \
                 : "+f"((c)[0]), "+f"((c)[1]), "+f"((c)[2]), "+f"((c)[3]) \
                 : "r"((a)[0]), "r"((a)[1]), "r"((a)[2]), "r"((a)[3]), \
                   "r"(b0v), "r"(b1v))

#define SWZ(x) ((uint32_t)(x) ^ ((((uint32_t)(x)) >> 3) & 0x70))

// exp2 on the MUFU pipe (scores pre-scaled into log2 domain)
__device__ __forceinline__ float fex2(float x) {
    float r;
    x = fmaxf(x, -126.f);
    asm("ex2.approx.f32 %0, %1;" : "=f"(r) : "f"(x));
    return r;
}

__device__ __forceinline__ uint32_t packhf(float x, float y) {
    __half2 h = __floats2half2_rn(x, y);
    return *(uint32_t*)&h;
}

// ---------------------------------------------------------------------------
// fp32 -> fp16 for X inputs. blockIdx.y selects slot.
// ---------------------------------------------------------------------------
__global__ __launch_bounds__(256)
void conv_x_kernel(const float* __restrict__ Q, const float* __restrict__ K,
                   const float* __restrict__ V)
{
    const int slot = blockIdx.y;
    const float* X = (slot == 0) ? Q : (slot == 1) ? K : V;
    size_t i = (size_t)blockIdx.x * 256 + threadIdx.x;
    float4 v = ((const float4*)X)[i];
    __half2* hp = reinterpret_cast<__half2*>(g_xh[slot] + i * 4);
    hp[0] = __floats2half2_rn(v.x, v.y);
    hp[1] = __floats2half2_rn(v.z, v.w);
}

// ---------------------------------------------------------------------------
// W [K][N] fp32 -> transposed [N][K] fp16. blockIdx.z selects slot.
// ---------------------------------------------------------------------------
__global__ __launch_bounds__(256)
void conv_w_kernel(const float* __restrict__ WQ, const float* __restrict__ WK,
                   const float* __restrict__ WV)
{
    __shared__ float t[32][33];
    const int slot = blockIdx.z;
    const float* W = (slot == 0) ? WQ : (slot == 1) ? WK : WV;
    const int n0 = blockIdx.x * 32, k0 = blockIdx.y * 32;
    const int tx = threadIdx.x & 31, ty = threadIdx.x >> 5;
#pragma unroll
    for (int r = 0; r < 32; r += 8)
        t[ty + r][tx] = W[(size_t)(k0 + ty + r) * DM + n0 + tx];
    __syncthreads();
#pragma unroll
    for (int r = 0; r < 32; r += 8) {
        int n = ty + r;
        g_wh[slot][(size_t)(n0 + n) * DIN + k0 + tx] = __float2half(t[tx][n]);
    }
}

// ---------------------------------------------------------------------------
// fp16 HMMA projection GEMM. 128x128 CTA tile, K-chunk 64 (128B rows, SW128
// swizzle), 3-stage cp.async pipeline, ONE barrier per chunk, 2 CTAs/SM.
// ---------------------------------------------------------------------------
#define PROJ_TILE_B   16384               // 128 rows * 128 B (one matrix)
#define PROJ_STAGE_B  (2 * PROJ_TILE_B)   // A + B per stage
#define PROJ_SMEM     (3 * PROJ_STAGE_B)  // 3 stages = 98304 B

__global__ __launch_bounds__(256, 2)
void proj_mma_kernel(const float* __restrict__ bias, int which)
{
    extern __shared__ char dsm[];
    const uint32_t sbase = smem_u32(dsm);

    const __half* Ah = g_xh[which];
    const __half* Bh = g_wh[which];

    const int tid  = threadIdx.x;
    const int wid  = tid >> 5, lane = tid & 31;
    const int wm   = wid & 1;
    const int wn   = wid >> 1;
    const int row0 = blockIdx.y * 128, col0 = blockIdx.x * 128;

    const int lrow  = tid >> 1;
    const int lhalf = tid & 1;
    const char* gA = (const char*)(Ah + (size_t)(row0 + lrow) * DIN);
    const char* gB = (const char*)(Bh + (size_t)(col0 + lrow) * DIN);

    const int r8 = lane & 7;
    const int arow = ((lane >> 3) & 1) * 8 + r8;
    const int acol = lane >> 4;

    float acc[4][4][4];
#pragma unroll
    for (int i = 0; i < 4; ++i)
#pragma unroll
        for (int j = 0; j < 4; ++j)
            acc[i][j][0] = acc[i][j][1] = acc[i][j][2] = acc[i][j][3] = 0.f;

    // prefetch chunks 0 and 1 into stages 0 and 1
#pragma unroll
    for (int pc = 0; pc < 2; ++pc) {
        const uint32_t st = sbase + (uint32_t)pc * PROJ_STAGE_B;
        const int kb = pc * 128;
#pragma unroll
        for (int i = 0; i < 4; ++i) {
            int ch = lhalf * 4 + i;
            uint32_t off = SWZ(lrow * 128 + ch * 16);
            CP16(st + off,               gA + kb + ch * 16);
            CP16(st + PROJ_TILE_B + off, gB + kb + ch * 16);
        }
        CP_COMMIT();
    }

    int stage = 0;            // stage holding chunk c
    int wstage = 2;           // stage to write chunk c+2 into
    for (int c = 0; c < 16; ++c) {
        if (c < 15) CP_WAIT1(); else CP_WAIT0();
        __syncthreads();      // single barrier: orders chunk c-1 reads before
                              // the writes below into stage (c+2)%3=(c-1)%3
        if (c + 2 < 16) {
            const uint32_t st = sbase + (uint32_t)wstage * PROJ_STAGE_B;
            const int kb = (c + 2) * 128;
#pragma unroll
            for (int i = 0; i < 4; ++i) {
                int ch = lhalf * 4 + i;
                uint32_t off = SWZ(lrow * 128 + ch * 16);
                CP16(st + off,               gA + kb + ch * 16);
                CP16(st + PROJ_TILE_B + off, gB + kb + ch * 16);
            }
            CP_COMMIT();
        }
        const uint32_t buf = sbase + (uint32_t)stage * PROJ_STAGE_B;

#pragma unroll
        for (int ks = 0; ks < 4; ++ks) {
            const int ch = ks * 2 + acol;
            uint32_t ah[4][4], bf[2][4];
#pragma unroll
            for (int mt = 0; mt < 4; ++mt) {
                uint32_t off = SWZ((wm * 64 + mt * 16 + arow) * 128 + ch * 16);
                LDSM_X4(ah[mt][0], ah[mt][1], ah[mt][2], ah[mt][3], buf + off);
            }
#pragma unroll
            for (int nh = 0; nh < 2; ++nh) {
                uint32_t off = SWZ((wn * 32 + nh * 16 + arow) * 128 + ch * 16);
                LDSM_X4(bf[nh][0], bf[nh][1], bf[nh][2], bf[nh][3],
                        buf + PROJ_TILE_B + off);
            }
#pragma unroll
            for (int mt = 0; mt < 4; ++mt)
#pragma unroll
                for (int nh = 0; nh < 2; ++nh) {
                    MMA_F16S(acc[mt][2 * nh],     ah[mt], bf[nh][0], bf[nh][2]);
                    MMA_F16S(acc[mt][2 * nh + 1], ah[mt], bf[nh][1], bf[nh][3]);
                }
        }
        stage  = (stage  == 2) ? 0 : stage + 1;
        wstage = (wstage == 2) ? 0 : wstage + 1;
    }

    // Epilogue: bias + fp16 [bh][s][hd]. q scaled by 0.125*log2(e).
    const int g  = lane >> 2;
    const int t2 = (lane & 3) * 2;
    const float scale = (which == 0) ? 0.125f * 1.44269504f : 1.0f;
    __half* dst = (which == 0) ? g_qh : (which == 1) ? g_kh : g_vh;
#pragma unroll
    for (int mt = 0; mt < 4; ++mt) {
        const int r0 = row0 + wm * 64 + mt * 16 + g;
        const int r1 = r0 + 8;
        const int bat = r0 >> 11;
        const int s0 = r0 & 2047, s1 = r1 & 2047;
#pragma unroll
        for (int nt = 0; nt < 4; ++nt) {
            const int col = col0 + wn * 32 + nt * 8 + t2;
            const float2 bv2 = *(const float2*)(bias + col);
            const int h = col >> 6, hd = col & 63;
            const int bh = bat * H_ + h;
            float v00 = (acc[mt][nt][0] + bv2.x) * scale;
            float v01 = (acc[mt][nt][1] + bv2.y) * scale;
            float v10 = (acc[mt][nt][2] + bv2.x) * scale;
            float v11 = (acc[mt][nt][3] + bv2.y) * scale;
            size_t o0 = ((size_t)bh * S_ + s0) * HD_ + hd;
            size_t o1 = ((size_t)bh * S_ + s1) * HD_ + hd;
            *(uint32_t*)(dst + o0) = packhf(v00, v01);
            *(uint32_t*)(dst + o1) = packhf(v10, v11);
        }
    }
}

// ---------------------------------------------------------------------------
// fp16 HMMA flash attention (log2-domain scores, MUFU ex2 softmax).
// BR=64, BC=64, 4 warps, 4 CTAs/SM. QK: qh x Kh. PV: Ph x Vh (ldmatrix.trans).
// smem: Q 8K @32768, double-buffered {Kh 8K, Vh 8K} @0/@16384 = 40KB
// ---------------------------------------------------------------------------
#define ATTN_SMEM (40960 + 1024)

__global__ __launch_bounds__(128, 4)
void attn_mma_kernel(float* __restrict__ out)
{
    extern __shared__ char asmem[];
    const uint32_t sb = (smem_u32(asmem) + 1023u) & ~1023u;

    const int tid  = threadIdx.x;
    const int lane = tid & 31, warp = tid >> 5;
    const int bh   = blockIdx.y;
    const int q0   = blockIdx.x * 64;

    const char* qh = (const char*)(g_qh + (size_t)bh * S_ * HD_);
    const char* kh = (const char*)(g_kh + (size_t)bh * S_ * HD_);
    const char* vh = (const char*)(g_vh + (size_t)bh * S_ * HD_);

    const int r8 = lane & 7;
    const int arow = ((lane >> 3) & 1) * 8 + r8;
    const int acol = lane >> 4;

    const int lrow  = tid >> 1;       // 0..63
    const int lhalf = tid & 1;

    // ---- stage Q tile [64][64] ----
#pragma unroll
    for (int i = 0; i < 4; ++i) {
        int ch = lhalf * 4 + i;
        uint32_t off = SWZ(lrow * 128 + ch * 16);
        CP16(sb + 32768 + off, qh + (size_t)(q0 + lrow) * 128 + ch * 16);
    }
    CP_COMMIT();
    // ---- chunk 0 into buf0 ----
#pragma unroll
    for (int i = 0; i < 4; ++i) {
        int ch = lhalf * 4 + i;
        uint32_t off = SWZ(lrow * 128 + ch * 16);
        CP16(sb + off,        kh + (size_t)lrow * 128 + ch * 16);
        CP16(sb + 8192 + off, vh + (size_t)lrow * 128 + ch * 16);
    }
    CP_COMMIT();
    CP_WAIT0();
    __syncthreads();

    // ---- Q fragments into registers ----
    uint32_t qa_h[4][4];
#pragma unroll
    for (int ks = 0; ks < 4; ++ks) {
        int row = warp * 16 + arow;
        int ch  = ks * 2 + acol;
        uint32_t off = SWZ(row * 128 + ch * 16);
        LDSM_X4(qa_h[ks][0], qa_h[ks][1], qa_h[ks][2], qa_h[ks][3], sb + 32768 + off);
    }

    float m0 = -1e30f, m1 = -1e30f, l0 = 0.f, l1 = 0.f;
    float o[8][4];
#pragma unroll
    for (int nt = 0; nt < 8; ++nt)
        o[nt][0] = o[nt][1] = o[nt][2] = o[nt][3] = 0.f;

    for (int c = 0; c < 32; ++c) {
        if (c > 0) CP_WAIT0();
        __syncthreads();
        if (c + 1 < 32) {
            const uint32_t nb = sb + (uint32_t)((c + 1) & 1) * 16384;
            const int kb = (c + 1) * 64;
#pragma unroll
            for (int i = 0; i < 4; ++i) {
                int ch = lhalf * 4 + i;
                uint32_t off = SWZ(lrow * 128 + ch * 16);
                CP16(nb + off,        kh + (size_t)(kb + lrow) * 128 + ch * 16);
                CP16(nb + 8192 + off, vh + (size_t)(kb + lrow) * 128 + ch * 16);
            }
            CP_COMMIT();
        }
        const uint32_t buf = sb + (uint32_t)(c & 1) * 16384;

        // ---- S = qh @ Kh^T  (log2-domain scores) ----
        float cc[8][4];
#pragma unroll
        for (int nt = 0; nt < 8; ++nt)
            cc[nt][0] = cc[nt][1] = cc[nt][2] = cc[nt][3] = 0.f;

#pragma unroll
        for (int ks = 0; ks < 4; ++ks) {
#pragma unroll
            for (int np = 0; np < 4; ++np) {
                uint32_t off = SWZ((np * 16 + arow) * 128 + (ks * 2 + acol) * 16);
                uint32_t b0, b1, b2, b3;
                LDSM_X4(b0, b1, b2, b3, buf + off);
                MMA_F16S(cc[2 * np],     qa_h[ks], b0, b2);
                MMA_F16S(cc[2 * np + 1], qa_h[ks], b1, b3);
            }
        }

        // ---- online softmax (exp2 on MUFU pipe) ----
        float rmx0 = cc[0][0], rmx1 = cc[0][2];
#pragma unroll
        for (int nt = 0; nt < 8; ++nt) {
            rmx0 = fmaxf(rmx0, fmaxf(cc[nt][0], cc[nt][1]));
            rmx1 = fmaxf(rmx1, fmaxf(cc[nt][2], cc[nt][3]));
        }
        rmx0 = fmaxf(rmx0, __shfl_xor_sync(0xffffffffu, rmx0, 1));
        rmx0 = fmaxf(rmx0, __shfl_xor_sync(0xffffffffu, rmx0, 2));
        rmx1 = fmaxf(rmx1, __shfl_xor_sync(0xffffffffu, rmx1, 1));
        rmx1 = fmaxf(rmx1, __shfl_xor_sync(0xffffffffu, rmx1, 2));
        float mn0 = fmaxf(m0, rmx0), mn1 = fmaxf(m1, rmx1);
        float cr0 = fex2(m0 - mn0), cr1 = fex2(m1 - mn1);
        m0 = mn0; m1 = mn1;
        float rs0 = 0.f, rs1 = 0.f;
#pragma unroll
        for (int nt = 0; nt < 8; ++nt) {
            cc[nt][0] = fex2(cc[nt][0] - mn0);
            cc[nt][1] = fex2(cc[nt][1] - mn0);
            cc[nt][2] = fex2(cc[nt][2] - mn1);
            cc[nt][3] = fex2(cc[nt][3] - mn1);
            rs0 += cc[nt][0] + cc[nt][1];
            rs1 += cc[nt][2] + cc[nt][3];
        }
        rs0 += __shfl_xor_sync(0xffffffffu, rs0, 1);
        rs0 += __shfl_xor_sync(0xffffffffu, rs0, 2);
        rs1 += __shfl_xor_sync(0xffffffffu, rs1, 1);
        rs1 += __shfl_xor_sync(0xffffffffu, rs1, 2);
        l0 = l0 * cr0 + rs0;
        l1 = l1 * cr1 + rs1;
#pragma unroll
        for (int nt = 0; nt < 8; ++nt) {
            o[nt][0] *= cr0; o[nt][1] *= cr0;
            o[nt][2] *= cr1; o[nt][3] *= cr1;
        }

        // ---- pack P into fp16 A fragments ----
        uint32_t pa_h[4][4];
#pragma unroll
        for (int j = 0; j < 4; ++j) {
            pa_h[j][0] = packhf(cc[2 * j][0],     cc[2 * j][1]);
            pa_h[j][1] = packhf(cc[2 * j][2],     cc[2 * j][3]);
            pa_h[j][2] = packhf(cc[2 * j + 1][0], cc[2 * j + 1][1]);
            pa_h[j][3] = packhf(cc[2 * j + 1][2], cc[2 * j + 1][3]);
        }

        // ---- O += Ph @ Vh ----
#pragma unroll
        for (int j = 0; j < 4; ++j) {
#pragma unroll
            for (int np = 0; np < 4; ++np) {
                uint32_t off = SWZ((j * 16 + arow) * 128 + (np * 2 + acol) * 16);
                uint32_t b0, b1, b2, b3;
                LDSM_X4T(b0, b1, b2, b3, buf + 8192 + off);
                MMA_F16S(o[2 * np],     pa_h[j], b0, b1);
                MMA_F16S(o[2 * np + 1], pa_h[j], b2, b3);
            }
        }
    }

    // ---- epilogue ----
    const int g  = lane >> 2;
    const int t2 = (lane & 3) * 2;
    const int bat = bh >> 4, h = bh & 15;
    const int s0 = q0 + warp * 16 + g, s1 = s0 + 8;
    const float inv0 = 1.0f / l0, inv1 = 1.0f / l1;
#pragma unroll
    for (int nt = 0; nt < 8; ++nt) {
        int col = h * HD_ + nt * 8 + t2;
        float2 v0, v1;
        v0.x = o[nt][0] * inv0; v0.y = o[nt][1] * inv0;
        v1.x = o[nt][2] * inv1; v1.y = o[nt][3] * inv1;
        *(float2*)(out + ((size_t)bat * S_ + s0) * DM + col) = v0;
        *(float2*)(out + ((size_t)bat * S_ + s1) * DM + col) = v1;
    }
}

// ---------------------------------------------------------------------------
extern "C" void kernel_launch(void* const* d_in, const int* in_sizes, int n_in,
                              void* d_out, int out_size)
{
    (void)in_sizes; (void)n_in; (void)out_size;
    const float* Q  = (const float*)d_in[0];
    const float* V  = (const float*)d_in[1];
    const float* K  = (const float*)d_in[2];
    const float* wq = (const float*)d_in[3];
    const float* bq = (const float*)d_in[4];
    const float* wk = (const float*)d_in[5];
    const float* bk = (const float*)d_in[6];
    const float* wv = (const float*)d_in[7];
    const float* bv = (const float*)d_in[8];
    float* out = (float*)d_out;

    dim3 xg((MX * DIN) / 4 / 256, 3);
    conv_x_kernel<<<xg, 256>>>(Q, K, V);
    dim3 wg(DM / 32, DIN / 32, 3);
    conv_w_kernel<<<wg, 256>>>(wq, wk, wv);

    cudaFuncSetAttribute(proj_mma_kernel, cudaFuncAttributeMaxDynamicSharedMemorySize, PROJ_SMEM);
    dim3 pg(DM / 128, MX / 128);
    proj_mma_kernel<<<pg, 256, PROJ_SMEM>>>(bq, 0);
    proj_mma_kernel<<<pg, 256, PROJ_SMEM>>>(bk, 1);
    proj_mma_kernel<<<pg, 256, PROJ_SMEM>>>(bv, 2);

    cudaFuncSetAttribute(attn_mma_kernel, cudaFuncAttributeMaxDynamicSharedMemorySize, ATTN_SMEM);
    dim3 ag(S_ / 64, B_ * H_);
    attn_mma_kernel<<<ag, 128, ATTN_SMEM>>>(out);
}